// round 10
// baseline (speedup 1.0000x reference)
#include <cuda_runtime.h>
#include <cstdint>

#define N_NODES 100000
#define N_EDGES 1600000
#define DIN 48
#define DOUT 128
#define OUT_ELEMS (N_NODES * DOUT)                     // 12,800,000
#define FULL_OUT  (OUT_ELEMS + 3 * N_EDGES + N_NODES)  // 17,700,000

#define SCAN_SLICES ((N_NODES + 1023) / 1024)          // 98

// Scratch node-feature buffers — written fully by gather, no zeroing.
__device__ float g_bufA[(size_t)N_NODES * DIN];
__device__ float g_bufB[(size_t)N_NODES * DIN];

// CSR-by-destination structures.
__device__ int    g_off[N_NODES + 1];
__device__ int    g_cursor[N_NODES];
__device__ int    g_bsum[SCAN_SLICES];
__device__ float2 g_epay[N_EDGES];         // {src_as_float_bits, dfs}

// Software grid barrier state (generation monotonically increases across replays).
__device__ int g_bar_ctr = 0;
__device__ int g_bar_gen = 0;

// Pre-split tf32 weights (hi/lo).
__device__ uint32_t g_W1h[48 * 128], g_W1l[48 * 128];
__device__ uint32_t g_W2h[128 * 128], g_W2l[128 * 128];

// ---------------------------------------------------------------------------
// tf32 helpers.
// ---------------------------------------------------------------------------
__device__ __forceinline__ void split_tf32(float x, uint32_t& hi, uint32_t& lo)
{
    float h, l;
    asm("cvt.rna.tf32.f32 %0, %1;" : "=f"(h) : "f"(x));
    float r = x - h;
    asm("cvt.rna.tf32.f32 %0, %1;" : "=f"(l) : "f"(r));
    hi = __float_as_uint(h);
    lo = __float_as_uint(l);
}

__device__ __forceinline__ void mma_tf32(float d[4],
                                         uint32_t a0, uint32_t a1, uint32_t a2, uint32_t a3,
                                         uint32_t b0, uint32_t b1)
{
    asm volatile("mma.sync.aligned.m16n8k8.row.col.f32.tf32.tf32.f32 "
                 "{%0,%1,%2,%3}, {%4,%5,%6,%7}, {%8,%9}, {%0,%1,%2,%3};"
                 : "+f"(d[0]), "+f"(d[1]), "+f"(d[2]), "+f"(d[3])
                 : "r"(a0), "r"(a1), "r"(a2), "r"(a3), "r"(b0), "r"(b1));
}

// ---------------------------------------------------------------------------
// Persistent single-kernel CSR build.
// 196 blocks x 256 threads, all co-resident (<=2 CTAs/SM) -> spin barrier safe.
// ---------------------------------------------------------------------------
#define CSR_BLOCKS 196
#define CSR_THREADS 256
#define CSR_GT (CSR_BLOCKS * CSR_THREADS)   // 50176

__device__ __forceinline__ void grid_barrier()
{
    __syncthreads();
    if (threadIdx.x == 0) {
        int gen = atomicAdd(&g_bar_gen, 0);
        __threadfence();
        if (atomicAdd(&g_bar_ctr, 1) == CSR_BLOCKS - 1) {
            atomicExch(&g_bar_ctr, 0);
            __threadfence();
            atomicExch(&g_bar_gen, gen + 1);
        } else {
            while (atomicAdd(&g_bar_gen, 0) == gen) { __nanosleep(64); }
        }
    }
    __syncthreads();
}

template <bool TAIL>
__global__ void __launch_bounds__(CSR_THREADS, 2)
build_csr(const int* __restrict__ sn, const int* __restrict__ en,
          const float* __restrict__ dfs, const float* __restrict__ df,
          const float* __restrict__ W1, const float* __restrict__ W2,
          float* __restrict__ out)
{
    __shared__ int sh[CSR_THREADS];
    const int tid  = threadIdx.x;
    const int gtid = blockIdx.x * CSR_THREADS + tid;

    // ---- phase 0: zero offsets; one-time weight split ----
    for (int i = gtid; i < N_NODES; i += CSR_GT) g_off[i] = 0;
    if (gtid < 128 * 128) {
        if (gtid < 48 * 128) split_tf32(__ldg(W1 + gtid), g_W1h[gtid], g_W1l[gtid]);
        split_tf32(__ldg(W2 + gtid), g_W2h[gtid], g_W2l[gtid]);
    }
    grid_barrier();

    // ---- phase 1: histogram (return-less atomics) ----
    for (int e = gtid; e < N_EDGES; e += CSR_GT)
        atomicAdd(&g_off[__ldg(en + e)], 1);
    grid_barrier();

    // ---- phase 2: per-slice (1024-node) sums ----
    if (blockIdx.x < SCAN_SLICES) {
        int base = blockIdx.x * 1024 + tid * 4;
        int s = 0;
        #pragma unroll
        for (int j = 0; j < 4; j++)
            s += (base + j < N_NODES) ? g_off[base + j] : 0;
        sh[tid] = s;
        __syncthreads();
        for (int d = 128; d > 0; d >>= 1) {
            if (tid < d) sh[tid] += sh[tid + d];
            __syncthreads();
        }
        if (tid == 0) g_bsum[blockIdx.x] = sh[0];
    }
    grid_barrier();

    // ---- phase 3: block 0 scans the 98 slice sums ----
    if (blockIdx.x == 0) {
        int v = (tid < SCAN_SLICES) ? g_bsum[tid] : 0;
        sh[tid] = v;
        __syncthreads();
        for (int d = 1; d < 256; d <<= 1) {
            int x = (tid >= d) ? sh[tid - d] : 0;
            __syncthreads();
            sh[tid] += x;
            __syncthreads();
        }
        if (tid < SCAN_SLICES) g_bsum[tid] = sh[tid] - v;
        if (tid == 0) g_off[N_NODES] = sh[255];
    }
    grid_barrier();

    // ---- phase 4: slice-local scan -> offsets & cursors (+ df echo) ----
    if (blockIdx.x < SCAN_SLICES) {
        int base = blockIdx.x * 1024 + tid * 4;
        int v[4];
        int s = 0;
        #pragma unroll
        for (int j = 0; j < 4; j++) {
            v[j] = (base + j < N_NODES) ? g_off[base + j] : 0;
            s += v[j];
        }
        sh[tid] = s;
        __syncthreads();
        for (int d = 1; d < 256; d <<= 1) {
            int x = (tid >= d) ? sh[tid - d] : 0;
            __syncthreads();
            sh[tid] += x;
            __syncthreads();
        }
        int ex = sh[tid] - s + g_bsum[blockIdx.x];
        #pragma unroll
        for (int j = 0; j < 4; j++) {
            if (base + j < N_NODES) {
                g_off[base + j]    = ex;
                g_cursor[base + j] = ex;
                if (TAIL)
                    out[OUT_ELEMS + 3 * N_EDGES + base + j] = __ldg(df + base + j);
            }
            ex += v[j];
        }
    }
    grid_barrier();

    // ---- phase 5: fill payloads (+ sn/en/dfs echo) ----
    for (int e = gtid; e < N_EDGES; e += CSR_GT) {
        int s = __ldg(sn + e);
        int d = __ldg(en + e);
        float f = __ldg(dfs + e);
        int pos = atomicAdd(&g_cursor[d], 1);
        g_epay[pos] = make_float2(__int_as_float(s), f);
        if (TAIL) {
            float* p = out + OUT_ELEMS;
            p[e]               = (float)s;
            p[N_EDGES + e]     = (float)d;
            p[2 * N_EDGES + e] = f;
        }
    }
}

// ---------------------------------------------------------------------------
// Gather pass: dst[n] = df[n] * sum_{e: end=n} src[start_e] * dfs_e
// 12 threads per node, one float4 chunk each, unrolled x4.
// ---------------------------------------------------------------------------
#define GB ((N_NODES * 12 + 255) / 256)     // 4688

__global__ void gather_pass(const float* __restrict__ src, float* __restrict__ dst,
                            const float* __restrict__ df)
{
    int t = blockIdx.x * blockDim.x + threadIdx.x;
    if (t >= N_NODES * 12) return;
    int n = t / 12;
    int q = t - n * 12;

    int o0 = __ldg(&g_off[n]);
    int o1 = __ldg(&g_off[n + 1]);

    float4 acc = make_float4(0.f, 0.f, 0.f, 0.f);
    int i = o0;
    for (; i + 4 <= o1; i += 4) {
        float2 p0 = __ldg(&g_epay[i]);
        float2 p1 = __ldg(&g_epay[i + 1]);
        float2 p2 = __ldg(&g_epay[i + 2]);
        float2 p3 = __ldg(&g_epay[i + 3]);
        float4 v0 = __ldg((const float4*)(src + (size_t)__float_as_int(p0.x) * DIN) + q);
        float4 v1 = __ldg((const float4*)(src + (size_t)__float_as_int(p1.x) * DIN) + q);
        float4 v2 = __ldg((const float4*)(src + (size_t)__float_as_int(p2.x) * DIN) + q);
        float4 v3 = __ldg((const float4*)(src + (size_t)__float_as_int(p3.x) * DIN) + q);
        acc.x = fmaf(v0.x, p0.y, acc.x); acc.y = fmaf(v0.y, p0.y, acc.y);
        acc.z = fmaf(v0.z, p0.y, acc.z); acc.w = fmaf(v0.w, p0.y, acc.w);
        acc.x = fmaf(v1.x, p1.y, acc.x); acc.y = fmaf(v1.y, p1.y, acc.y);
        acc.z = fmaf(v1.z, p1.y, acc.z); acc.w = fmaf(v1.w, p1.y, acc.w);
        acc.x = fmaf(v2.x, p2.y, acc.x); acc.y = fmaf(v2.y, p2.y, acc.y);
        acc.z = fmaf(v2.z, p2.y, acc.z); acc.w = fmaf(v2.w, p2.y, acc.w);
        acc.x = fmaf(v3.x, p3.y, acc.x); acc.y = fmaf(v3.y, p3.y, acc.y);
        acc.z = fmaf(v3.z, p3.y, acc.z); acc.w = fmaf(v3.w, p3.y, acc.w);
    }
    for (; i < o1; i++) {
        float2 p = __ldg(&g_epay[i]);
        float4 v = __ldg((const float4*)(src + (size_t)__float_as_int(p.x) * DIN) + q);
        acc.x = fmaf(v.x, p.y, acc.x); acc.y = fmaf(v.y, p.y, acc.y);
        acc.z = fmaf(v.z, p.y, acc.z); acc.w = fmaf(v.w, p.y, acc.w);
    }

    float f = __ldg(df + n);
    acc.x *= f; acc.y *= f; acc.z *= f; acc.w *= f;
    ((float4*)(dst + (size_t)n * DIN))[q] = acc;
}

// ---------------------------------------------------------------------------
// Persistent fused MLP on tensor cores (tf32 mma.sync, 3xTF32 compensation):
//   out = relu(x @ W1 + b1) @ W2 + b2
// ---------------------------------------------------------------------------
#define MLP_TM 128
#define MLP_THREADS 256
#define MLP_GRID 148
#define N_TILES ((N_NODES + MLP_TM - 1) / MLP_TM)      // 782
#define W_STRIDE 136
#define YT_STRIDE 52
#define MLP_SMEM_WORDS (48*W_STRIDE*2 + 128*W_STRIDE*2 + 256 + MLP_TM*YT_STRIDE)

__global__ void __launch_bounds__(MLP_THREADS, 1)
mlp_kernel(const float* __restrict__ x,
           const float* __restrict__ b1, const float* __restrict__ b2,
           float* __restrict__ out)
{
    extern __shared__ uint32_t smu[];
    uint32_t* W1hs = smu;                         // [48][136]
    uint32_t* W1ls = W1hs + 48 * W_STRIDE;
    uint32_t* W2hs = W1ls + 48 * W_STRIDE;        // [128][136]
    uint32_t* W2ls = W2hs + 128 * W_STRIDE;
    float*    b1s  = (float*)(W2ls + 128 * W_STRIDE);
    float*    b2s  = b1s + 128;
    float*    yt   = b2s + 128;                   // [128][52]

    int tid = threadIdx.x;

    for (int i = tid; i < 48 * 128; i += MLP_THREADS) {
        int k = i >> 7, n = i & 127;
        W1hs[k * W_STRIDE + n] = g_W1h[i];
        W1ls[k * W_STRIDE + n] = g_W1l[i];
    }
    for (int i = tid; i < 128 * 128; i += MLP_THREADS) {
        int k = i >> 7, n = i & 127;
        W2hs[k * W_STRIDE + n] = g_W2h[i];
        W2ls[k * W_STRIDE + n] = g_W2l[i];
    }
    if (tid < 128) { b1s[tid] = __ldg(b1 + tid); b2s[tid] = __ldg(b2 + tid); }

    int warp = tid >> 5;
    int lane = tid & 31;
    int r = lane >> 2;
    int c = lane & 3;
    int srcA = (lane & ~3) | (c >> 1);
    int srcB = srcA + 2;
    bool odd = (c & 1);

    for (int tile = blockIdx.x; tile < N_TILES; tile += MLP_GRID) {
        int node0 = tile * MLP_TM;

        __syncthreads();
        for (int i = tid; i < MLP_TM * 48; i += MLP_THREADS) {
            int rr = i / 48;
            int n = node0 + rr;
            yt[rr * YT_STRIDE + (i - rr * 48)] =
                (n < N_NODES) ? __ldg(x + (size_t)n * 48 + (i - rr * 48)) : 0.f;
        }
        __syncthreads();

        float d[16][4];
        float h[16][4];

        // ---- stage 1: H = relu(Y @ W1 + b1), K = 48 ----
        #pragma unroll
        for (int nt = 0; nt < 16; nt++) {
            d[nt][0] = b1s[nt * 8 + 2 * c];
            d[nt][1] = b1s[nt * 8 + 2 * c + 1];
            d[nt][2] = d[nt][0];
            d[nt][3] = d[nt][1];
        }
        {
            const float* yb = yt + warp * 16 * YT_STRIDE;
            #pragma unroll
            for (int ks = 0; ks < 6; ks++) {
                int k0 = ks * 8;
                uint32_t ah[4], al[4];
                split_tf32(yb[r * YT_STRIDE + k0 + c],           ah[0], al[0]);
                split_tf32(yb[(r + 8) * YT_STRIDE + k0 + c],     ah[1], al[1]);
                split_tf32(yb[r * YT_STRIDE + k0 + c + 4],       ah[2], al[2]);
                split_tf32(yb[(r + 8) * YT_STRIDE + k0 + c + 4], ah[3], al[3]);
                #pragma unroll
                for (int nt = 0; nt < 16; nt++) {
                    uint32_t bh0 = W1hs[(k0 + c) * W_STRIDE + nt * 8 + r];
                    uint32_t bh1 = W1hs[(k0 + c + 4) * W_STRIDE + nt * 8 + r];
                    uint32_t bl0 = W1ls[(k0 + c) * W_STRIDE + nt * 8 + r];
                    uint32_t bl1 = W1ls[(k0 + c + 4) * W_STRIDE + nt * 8 + r];
                    mma_tf32(d[nt], ah[0], ah[1], ah[2], ah[3], bh0, bh1);
                    mma_tf32(d[nt], al[0], al[1], al[2], al[3], bh0, bh1);
                    mma_tf32(d[nt], ah[0], ah[1], ah[2], ah[3], bl0, bl1);
                }
            }
        }
        #pragma unroll
        for (int nt = 0; nt < 16; nt++) {
            h[nt][0] = fmaxf(d[nt][0], 0.f);
            h[nt][1] = fmaxf(d[nt][1], 0.f);
            h[nt][2] = fmaxf(d[nt][2], 0.f);
            h[nt][3] = fmaxf(d[nt][3], 0.f);
        }

        // ---- stage 2: OUT = H @ W2 + b2, K = 128 ----
        #pragma unroll
        for (int nt = 0; nt < 16; nt++) {
            d[nt][0] = b2s[nt * 8 + 2 * c];
            d[nt][1] = b2s[nt * 8 + 2 * c + 1];
            d[nt][2] = d[nt][0];
            d[nt][3] = d[nt][1];
        }
        #pragma unroll
        for (int ks = 0; ks < 16; ks++) {
            int k0 = ks * 8;
            float w0 = __shfl_sync(0xFFFFFFFFu, h[ks][0], srcA);
            float w1 = __shfl_sync(0xFFFFFFFFu, h[ks][1], srcA);
            float w2 = __shfl_sync(0xFFFFFFFFu, h[ks][2], srcA);
            float w3 = __shfl_sync(0xFFFFFFFFu, h[ks][3], srcA);
            float x0 = __shfl_sync(0xFFFFFFFFu, h[ks][0], srcB);
            float x1 = __shfl_sync(0xFFFFFFFFu, h[ks][1], srcB);
            float x2 = __shfl_sync(0xFFFFFFFFu, h[ks][2], srcB);
            float x3 = __shfl_sync(0xFFFFFFFFu, h[ks][3], srcB);
            uint32_t ah[4], al[4];
            split_tf32(odd ? w1 : w0, ah[0], al[0]);
            split_tf32(odd ? w3 : w2, ah[1], al[1]);
            split_tf32(odd ? x1 : x0, ah[2], al[2]);
            split_tf32(odd ? x3 : x2, ah[3], al[3]);
            #pragma unroll
            for (int nt = 0; nt < 16; nt++) {
                uint32_t bh0 = W2hs[(k0 + c) * W_STRIDE + nt * 8 + r];
                uint32_t bh1 = W2hs[(k0 + c + 4) * W_STRIDE + nt * 8 + r];
                uint32_t bl0 = W2ls[(k0 + c) * W_STRIDE + nt * 8 + r];
                uint32_t bl1 = W2ls[(k0 + c + 4) * W_STRIDE + nt * 8 + r];
                mma_tf32(d[nt], ah[0], ah[1], ah[2], ah[3], bh0, bh1);
                mma_tf32(d[nt], al[0], al[1], al[2], al[3], bh0, bh1);
                mma_tf32(d[nt], ah[0], ah[1], ah[2], ah[3], bl0, bl1);
            }
        }
        {
            int row0 = node0 + warp * 16 + r;
            int row1 = row0 + 8;
            #pragma unroll
            for (int nt = 0; nt < 16; nt++) {
                if (row0 < N_NODES)
                    *(float2*)(out + (size_t)row0 * 128 + nt * 8 + 2 * c) =
                        make_float2(d[nt][0], d[nt][1]);
                if (row1 < N_NODES)
                    *(float2*)(out + (size_t)row1 * 128 + nt * 8 + 2 * c) =
                        make_float2(d[nt][2], d[nt][3]);
            }
        }
    }
}

extern "C" void kernel_launch(void* const* d_in, const int* in_sizes, int n_in,
                              void* d_out, int out_size)
{
    const float* y   = (const float*)d_in[0];
    const int*   sn  = (const int*)  d_in[1];
    const int*   en  = (const int*)  d_in[2];
    const float* dfs = (const float*)d_in[3];
    const float* df  = (const float*)d_in[4];
    const float* W1  = (const float*)d_in[5];
    const float* b1  = (const float*)d_in[6];
    const float* W2  = (const float*)d_in[7];
    const float* b2  = (const float*)d_in[8];
    float* out = (float*)d_out;

    float *bufA, *bufB;
    cudaGetSymbolAddress((void**)&bufA, g_bufA);
    cudaGetSymbolAddress((void**)&bufB, g_bufB);

    cudaFuncSetAttribute(mlp_kernel, cudaFuncAttributeMaxDynamicSharedMemorySize,
                         MLP_SMEM_WORDS * (int)sizeof(uint32_t));

    // ---- single-kernel CSR build (weight split + echoes folded in) ----
    if (out_size >= FULL_OUT) {
        build_csr<true><<<CSR_BLOCKS, CSR_THREADS>>>(sn, en, dfs, df, W1, W2, out);
    } else {
        build_csr<false><<<CSR_BLOCKS, CSR_THREADS>>>(sn, en, dfs, df, W1, W2, out);
    }

    // ---- two gather passes ----
    gather_pass<<<GB, 256>>>(y,    bufA, df);
    gather_pass<<<GB, 256>>>(bufA, bufB, df);

    // ---- persistent fused tensor-core MLP ----
    mlp_kernel<<<MLP_GRID, MLP_THREADS,
                 MLP_SMEM_WORDS * sizeof(uint32_t)>>>(bufB, b1, b2, out);
}

// round 11
// speedup vs baseline: 1.0810x; 1.0810x over previous
#include <cuda_runtime.h>
#include <cstdint>

#define N_NODES 100000
#define N_EDGES 1600000
#define DIN 48
#define DOUT 128
#define OUT_ELEMS (N_NODES * DOUT)                     // 12,800,000
#define FULL_OUT  (OUT_ELEMS + 3 * N_EDGES + N_NODES)  // 17,700,000

#define SCAN_BLOCKS ((N_NODES + 1023) / 1024)          // 98

// Scratch node-feature buffers — written fully by gather, no zeroing.
__device__ float g_bufA[(size_t)N_NODES * DIN];
__device__ float g_bufB[(size_t)N_NODES * DIN];

// CSR-by-destination structures.
__device__ int    g_off[N_NODES + 1];
__device__ int    g_cursor[N_NODES];
__device__ int    g_bsum[SCAN_BLOCKS];
__device__ int    g_scan_ctr;              // zero-init; reset by last block
__device__ float2 g_epay[N_EDGES];         // {src_as_float_bits, dfs}

// Pre-split tf32 weights (hi/lo).
__device__ uint32_t g_W1h[48 * 128], g_W1l[48 * 128];
__device__ uint32_t g_W2h[128 * 128], g_W2l[128 * 128];

// ---------------------------------------------------------------------------
// tf32 helpers.
// ---------------------------------------------------------------------------
__device__ __forceinline__ void split_tf32(float x, uint32_t& hi, uint32_t& lo)
{
    float h, l;
    asm("cvt.rna.tf32.f32 %0, %1;" : "=f"(h) : "f"(x));
    float r = x - h;
    asm("cvt.rna.tf32.f32 %0, %1;" : "=f"(l) : "f"(r));
    hi = __float_as_uint(h);
    lo = __float_as_uint(l);
}

__device__ __forceinline__ void mma_tf32(float d[4],
                                         uint32_t a0, uint32_t a1, uint32_t a2, uint32_t a3,
                                         uint32_t b0, uint32_t b1)
{
    asm volatile("mma.sync.aligned.m16n8k8.row.col.f32.tf32.tf32.f32 "
                 "{%0,%1,%2,%3}, {%4,%5,%6,%7}, {%8,%9}, {%0,%1,%2,%3};"
                 : "+f"(d[0]), "+f"(d[1]), "+f"(d[2]), "+f"(d[3])
                 : "r"(a0), "r"(a1), "r"(a2), "r"(a3), "r"(b0), "r"(b1));
}

// ---------------------------------------------------------------------------
// hist (x4 edges/thread, return-less atomics) + weight split fused.
// ---------------------------------------------------------------------------
#define HB  ((N_EDGES / 4 + 255) / 256)     // 1563
#define WB  64                              // 16384 / 256

__global__ void hist_and_split(const int* __restrict__ en,
                               const float* __restrict__ W1, const float* __restrict__ W2)
{
    if (blockIdx.x < HB) {
        int e0 = (blockIdx.x * blockDim.x + threadIdx.x) * 4;
        if (e0 + 4 <= N_EDGES) {
            int4 d4 = *(const int4*)(en + e0);
            atomicAdd(&g_off[d4.x], 1);
            atomicAdd(&g_off[d4.y], 1);
            atomicAdd(&g_off[d4.z], 1);
            atomicAdd(&g_off[d4.w], 1);
        } else {
            for (int e = e0; e < N_EDGES; e++)
                atomicAdd(&g_off[__ldg(en + e)], 1);
        }
    } else {
        int i = (blockIdx.x - HB) * blockDim.x + threadIdx.x;
        if (i < 48 * 128)  split_tf32(__ldg(W1 + i), g_W1h[i], g_W1l[i]);
        if (i < 128 * 128) split_tf32(__ldg(W2 + i), g_W2h[i], g_W2l[i]);
    }
}

// ---------------------------------------------------------------------------
// scanA+scanB fused (last-block-arrival pattern).
// ---------------------------------------------------------------------------
__global__ void scanAB()
{
    __shared__ int sh[256];
    __shared__ bool is_last;
    int tid = threadIdx.x;
    int base = blockIdx.x * 1024 + tid * 4;
    int s = 0;
    #pragma unroll
    for (int j = 0; j < 4; j++)
        s += (base + j < N_NODES) ? g_off[base + j] : 0;
    sh[tid] = s;
    __syncthreads();
    for (int d = 128; d > 0; d >>= 1) {
        if (tid < d) sh[tid] += sh[tid + d];
        __syncthreads();
    }
    if (tid == 0) {
        g_bsum[blockIdx.x] = sh[0];
        __threadfence();
        int c = atomicAdd(&g_scan_ctr, 1);
        is_last = (c == gridDim.x - 1);
    }
    __syncthreads();
    if (!is_last) return;

    int v = (tid < SCAN_BLOCKS) ? __ldcg(&g_bsum[tid]) : 0;
    __syncthreads();
    sh[tid] = v;
    __syncthreads();
    for (int d = 1; d < 256; d <<= 1) {
        int x = (tid >= d) ? sh[tid - d] : 0;
        __syncthreads();
        sh[tid] += x;
        __syncthreads();
    }
    if (tid < SCAN_BLOCKS) g_bsum[tid] = sh[tid] - v;
    if (tid == 0) { g_off[N_NODES] = sh[255]; g_scan_ctr = 0; }
}

// ---------------------------------------------------------------------------
// Phase C: block-local exclusive scan + block prefix; offsets & cursors.
// TAIL: also echoes df into the output (coalesced DRAM STG, free here).
// ---------------------------------------------------------------------------
template <bool TAIL>
__global__ void scanC(const float* __restrict__ df, float* __restrict__ out)
{
    __shared__ int sh[256];
    int tid = threadIdx.x;
    int base = blockIdx.x * 1024 + tid * 4;
    int v[4];
    int s = 0;
    #pragma unroll
    for (int j = 0; j < 4; j++) {
        v[j] = (base + j < N_NODES) ? g_off[base + j] : 0;
        s += v[j];
    }
    sh[tid] = s;
    __syncthreads();
    for (int d = 1; d < 256; d <<= 1) {
        int x = (tid >= d) ? sh[tid - d] : 0;
        __syncthreads();
        sh[tid] += x;
        __syncthreads();
    }
    int ex = sh[tid] - s + g_bsum[blockIdx.x];
    #pragma unroll
    for (int j = 0; j < 4; j++) {
        if (base + j < N_NODES) {
            g_off[base + j]    = ex;
            g_cursor[base + j] = ex;
            if (TAIL)
                out[OUT_ELEMS + 3 * N_EDGES + base + j] = __ldg(df + base + j);
        }
        ex += v[j];
    }
}

// ---------------------------------------------------------------------------
// fill: ONE edge per thread (max TLP on the 318-cyc atomic chain — R9's x4
// unroll regressed). TAIL: echoes sn/en/dfs as coalesced scalar stores.
// ---------------------------------------------------------------------------
#define EB ((N_EDGES + 255) / 256)          // 6250

template <bool TAIL>
__global__ void fill_kernel(const int* __restrict__ sn, const int* __restrict__ en,
                            const float* __restrict__ dfs, float* __restrict__ out)
{
    int e = blockIdx.x * blockDim.x + threadIdx.x;
    if (e >= N_EDGES) return;
    int s = __ldg(sn + e);
    int d = __ldg(en + e);
    float f = __ldg(dfs + e);
    int pos = atomicAdd(&g_cursor[d], 1);
    g_epay[pos] = make_float2(__int_as_float(s), f);
    if (TAIL) {
        float* p = out + OUT_ELEMS;
        p[e]               = (float)s;
        p[N_EDGES + e]     = (float)d;
        p[2 * N_EDGES + e] = f;
    }
}

// ---------------------------------------------------------------------------
// Gather pass: dst[n] = df[n] * sum_{e: end=n} src[start_e] * dfs_e
// 12 threads per node, one float4 chunk each, unrolled x4.
// ---------------------------------------------------------------------------
#define GB ((N_NODES * 12 + 255) / 256)     // 4688

__global__ void gather_pass(const float* __restrict__ src, float* __restrict__ dst,
                            const float* __restrict__ df)
{
    int t = blockIdx.x * blockDim.x + threadIdx.x;
    if (t >= N_NODES * 12) return;
    int n = t / 12;
    int q = t - n * 12;

    int o0 = __ldg(&g_off[n]);
    int o1 = __ldg(&g_off[n + 1]);

    float4 acc = make_float4(0.f, 0.f, 0.f, 0.f);
    int i = o0;
    for (; i + 4 <= o1; i += 4) {
        float2 p0 = __ldg(&g_epay[i]);
        float2 p1 = __ldg(&g_epay[i + 1]);
        float2 p2 = __ldg(&g_epay[i + 2]);
        float2 p3 = __ldg(&g_epay[i + 3]);
        float4 v0 = __ldg((const float4*)(src + (size_t)__float_as_int(p0.x) * DIN) + q);
        float4 v1 = __ldg((const float4*)(src + (size_t)__float_as_int(p1.x) * DIN) + q);
        float4 v2 = __ldg((const float4*)(src + (size_t)__float_as_int(p2.x) * DIN) + q);
        float4 v3 = __ldg((const float4*)(src + (size_t)__float_as_int(p3.x) * DIN) + q);
        acc.x = fmaf(v0.x, p0.y, acc.x); acc.y = fmaf(v0.y, p0.y, acc.y);
        acc.z = fmaf(v0.z, p0.y, acc.z); acc.w = fmaf(v0.w, p0.y, acc.w);
        acc.x = fmaf(v1.x, p1.y, acc.x); acc.y = fmaf(v1.y, p1.y, acc.y);
        acc.z = fmaf(v1.z, p1.y, acc.z); acc.w = fmaf(v1.w, p1.y, acc.w);
        acc.x = fmaf(v2.x, p2.y, acc.x); acc.y = fmaf(v2.y, p2.y, acc.y);
        acc.z = fmaf(v2.z, p2.y, acc.z); acc.w = fmaf(v2.w, p2.y, acc.w);
        acc.x = fmaf(v3.x, p3.y, acc.x); acc.y = fmaf(v3.y, p3.y, acc.y);
        acc.z = fmaf(v3.z, p3.y, acc.z); acc.w = fmaf(v3.w, p3.y, acc.w);
    }
    for (; i < o1; i++) {
        float2 p = __ldg(&g_epay[i]);
        float4 v = __ldg((const float4*)(src + (size_t)__float_as_int(p.x) * DIN) + q);
        acc.x = fmaf(v.x, p.y, acc.x); acc.y = fmaf(v.y, p.y, acc.y);
        acc.z = fmaf(v.z, p.y, acc.z); acc.w = fmaf(v.w, p.y, acc.w);
    }

    float f = __ldg(df + n);
    acc.x *= f; acc.y *= f; acc.z *= f; acc.w *= f;
    ((float4*)(dst + (size_t)n * DIN))[q] = acc;
}

// ---------------------------------------------------------------------------
// Persistent fused MLP on tensor cores (tf32 mma.sync, 3xTF32 compensation):
//   out = relu(x @ W1 + b1) @ W2 + b2
// 512 threads/CTA = 16 warps/SM (2x the warps of R10). Each warp owns a
// 16-node group end-to-end and grid-strides independently (no syncs in the
// mainloop). Smem holds ONLY the pre-split weights (188KB). Stage-1 A comes
// straight from L2-resident x; H is streamed in 64-col halves so the
// accumulator set is d2[16][4] + h[8][4] = 96 floats -> fits 512 threads.
// Accumulation order identical to R7-R10 (bit-identical results).
// ---------------------------------------------------------------------------
#define MLP_THREADS 512
#define MLP_GRID 148
#define MLP_WARPS (MLP_GRID * (MLP_THREADS / 32))      // 2368
#define N_GROUPS ((N_NODES + 15) / 16)                 // 6250
#define W_STRIDE 136
#define MLP_SMEM_WORDS (48*W_STRIDE*2 + 128*W_STRIDE*2 + 256)   // 48128 words

__global__ void __launch_bounds__(MLP_THREADS, 1)
mlp_kernel(const float* __restrict__ x,
           const float* __restrict__ b1, const float* __restrict__ b2,
           float* __restrict__ out)
{
    extern __shared__ uint32_t smu[];
    uint32_t* W1hs = smu;                         // [48][136]
    uint32_t* W1ls = W1hs + 48 * W_STRIDE;
    uint32_t* W2hs = W1ls + 48 * W_STRIDE;        // [128][136]
    uint32_t* W2ls = W2hs + 128 * W_STRIDE;
    float*    b1s  = (float*)(W2ls + 128 * W_STRIDE);
    float*    b2s  = b1s + 128;

    int tid = threadIdx.x;

    for (int i = tid; i < 48 * 128; i += MLP_THREADS) {
        int k = i >> 7, n = i & 127;
        W1hs[k * W_STRIDE + n] = g_W1h[i];
        W1ls[k * W_STRIDE + n] = g_W1l[i];
    }
    for (int i = tid; i < 128 * 128; i += MLP_THREADS) {
        int k = i >> 7, n = i & 127;
        W2hs[k * W_STRIDE + n] = g_W2h[i];
        W2ls[k * W_STRIDE + n] = g_W2l[i];
    }
    if (tid < 128) { b1s[tid] = __ldg(b1 + tid); b2s[tid] = __ldg(b2 + tid); }
    __syncthreads();

    int warp = tid >> 5;
    int lane = tid & 31;
    int r = lane >> 2;
    int c = lane & 3;
    int srcA = (lane & ~3) | (c >> 1);
    int srcB = srcA + 2;
    bool odd = (c & 1);

    for (int g = blockIdx.x * (MLP_THREADS / 32) + warp; g < N_GROUPS; g += MLP_WARPS) {
        int node0 = g * 16;
        int row0 = node0 + r;
        int row1 = row0 + 8;
        bool ok0 = row0 < N_NODES;
        bool ok1 = row1 < N_NODES;
        const float* y0 = x + (size_t)row0 * DIN;
        const float* y1 = x + (size_t)row1 * DIN;

        float d2[16][4];
        #pragma unroll
        for (int nt = 0; nt < 16; nt++) {
            d2[nt][0] = b2s[nt * 8 + 2 * c];
            d2[nt][1] = b2s[nt * 8 + 2 * c + 1];
            d2[nt][2] = d2[nt][0];
            d2[nt][3] = d2[nt][1];
        }

        #pragma unroll
        for (int half = 0; half < 2; half++) {
            // ---- stage 1 (half): H[:, half*64 .. half*64+63] ----
            float h[8][4];
            #pragma unroll
            for (int nt = 0; nt < 8; nt++) {
                int n0 = half * 64 + nt * 8;
                h[nt][0] = b1s[n0 + 2 * c];
                h[nt][1] = b1s[n0 + 2 * c + 1];
                h[nt][2] = h[nt][0];
                h[nt][3] = h[nt][1];
            }
            #pragma unroll
            for (int ks = 0; ks < 6; ks++) {
                int k0 = ks * 8;
                float a0 = ok0 ? __ldg(y0 + k0 + c)     : 0.f;
                float a1 = ok1 ? __ldg(y1 + k0 + c)     : 0.f;
                float a2 = ok0 ? __ldg(y0 + k0 + c + 4) : 0.f;
                float a3 = ok1 ? __ldg(y1 + k0 + c + 4) : 0.f;
                uint32_t ah[4], al[4];
                split_tf32(a0, ah[0], al[0]);
                split_tf32(a1, ah[1], al[1]);
                split_tf32(a2, ah[2], al[2]);
                split_tf32(a3, ah[3], al[3]);
                #pragma unroll
                for (int nt = 0; nt < 8; nt++) {
                    int ncol = half * 64 + nt * 8 + r;
                    uint32_t bh0 = W1hs[(k0 + c) * W_STRIDE + ncol];
                    uint32_t bh1 = W1hs[(k0 + c + 4) * W_STRIDE + ncol];
                    uint32_t bl0 = W1ls[(k0 + c) * W_STRIDE + ncol];
                    uint32_t bl1 = W1ls[(k0 + c + 4) * W_STRIDE + ncol];
                    mma_tf32(h[nt], ah[0], ah[1], ah[2], ah[3], bh0, bh1);
                    mma_tf32(h[nt], al[0], al[1], al[2], al[3], bh0, bh1);
                    mma_tf32(h[nt], ah[0], ah[1], ah[2], ah[3], bl0, bl1);
                }
            }
            #pragma unroll
            for (int nt = 0; nt < 8; nt++) {
                h[nt][0] = fmaxf(h[nt][0], 0.f);
                h[nt][1] = fmaxf(h[nt][1], 0.f);
                h[nt][2] = fmaxf(h[nt][2], 0.f);
                h[nt][3] = fmaxf(h[nt][3], 0.f);
            }

            // ---- stage 2 partial: d2 += H[:, k0..k0+7] @ W2[k0..k0+7, :] ----
            #pragma unroll
            for (int ks2 = 0; ks2 < 8; ks2++) {
                int k0 = half * 64 + ks2 * 8;
                float w0 = __shfl_sync(0xFFFFFFFFu, h[ks2][0], srcA);
                float w1 = __shfl_sync(0xFFFFFFFFu, h[ks2][1], srcA);
                float w2 = __shfl_sync(0xFFFFFFFFu, h[ks2][2], srcA);
                float w3 = __shfl_sync(0xFFFFFFFFu, h[ks2][3], srcA);
                float x0 = __shfl_sync(0xFFFFFFFFu, h[ks2][0], srcB);
                float x1 = __shfl_sync(0xFFFFFFFFu, h[ks2][1], srcB);
                float x2 = __shfl_sync(0xFFFFFFFFu, h[ks2][2], srcB);
                float x3 = __shfl_sync(0xFFFFFFFFu, h[ks2][3], srcB);
                uint32_t ah[4], al[4];
                split_tf32(odd ? w1 : w0, ah[0], al[0]);
                split_tf32(odd ? w3 : w2, ah[1], al[1]);
                split_tf32(odd ? x1 : x0, ah[2], al[2]);
                split_tf32(odd ? x3 : x2, ah[3], al[3]);
                #pragma unroll
                for (int nt = 0; nt < 16; nt++) {
                    uint32_t bh0 = W2hs[(k0 + c) * W_STRIDE + nt * 8 + r];
                    uint32_t bh1 = W2hs[(k0 + c + 4) * W_STRIDE + nt * 8 + r];
                    uint32_t bl0 = W2ls[(k0 + c) * W_STRIDE + nt * 8 + r];
                    uint32_t bl1 = W2ls[(k0 + c + 4) * W_STRIDE + nt * 8 + r];
                    mma_tf32(d2[nt], ah[0], ah[1], ah[2], ah[3], bh0, bh1);
                    mma_tf32(d2[nt], al[0], al[1], al[2], al[3], bh0, bh1);
                    mma_tf32(d2[nt], ah[0], ah[1], ah[2], ah[3], bl0, bl1);
                }
            }
        }

        // ---- store ----
        #pragma unroll
        for (int nt = 0; nt < 16; nt++) {
            if (ok0)
                *(float2*)(out + (size_t)row0 * 128 + nt * 8 + 2 * c) =
                    make_float2(d2[nt][0], d2[nt][1]);
            if (ok1)
                *(float2*)(out + (size_t)row1 * 128 + nt * 8 + 2 * c) =
                    make_float2(d2[nt][2], d2[nt][3]);
        }
    }
}

extern "C" void kernel_launch(void* const* d_in, const int* in_sizes, int n_in,
                              void* d_out, int out_size)
{
    const float* y   = (const float*)d_in[0];
    const int*   sn  = (const int*)  d_in[1];
    const int*   en  = (const int*)  d_in[2];
    const float* dfs = (const float*)d_in[3];
    const float* df  = (const float*)d_in[4];
    const float* W1  = (const float*)d_in[5];
    const float* b1  = (const float*)d_in[6];
    const float* W2  = (const float*)d_in[7];
    const float* b2  = (const float*)d_in[8];
    float* out = (float*)d_out;

    float *bufA, *bufB;
    cudaGetSymbolAddress((void**)&bufA, g_bufA);
    cudaGetSymbolAddress((void**)&bufB, g_bufB);
    int* offp;
    cudaGetSymbolAddress((void**)&offp, g_off);

    cudaFuncSetAttribute(mlp_kernel, cudaFuncAttributeMaxDynamicSharedMemorySize,
                         MLP_SMEM_WORDS * (int)sizeof(uint32_t));

    const bool tail = (out_size >= FULL_OUT);

    // ---- CSR build (by destination), weight split + echoes overlapped ----
    cudaMemsetAsync(offp, 0, N_NODES * sizeof(int));
    hist_and_split<<<HB + WB, 256>>>(en, W1, W2);
    scanAB<<<SCAN_BLOCKS, 256>>>();
    if (tail) {
        scanC<true><<<SCAN_BLOCKS, 256>>>(df, out);
        fill_kernel<true><<<EB, 256>>>(sn, en, dfs, out);
    } else {
        scanC<false><<<SCAN_BLOCKS, 256>>>(df, out);
        fill_kernel<false><<<EB, 256>>>(sn, en, dfs, out);
    }

    // ---- two gather passes ----
    gather_pass<<<GB, 256>>>(y,    bufA, df);
    gather_pass<<<GB, 256>>>(bufA, bufB, df);

    // ---- persistent fused tensor-core MLP (16 warps/SM) ----
    mlp_kernel<<<MLP_GRID, MLP_THREADS,
                 MLP_SMEM_WORDS * sizeof(uint32_t)>>>(bufB, b1, b2, out);
}

// round 12
// speedup vs baseline: 1.1132x; 1.0297x over previous
#include <cuda_runtime.h>
#include <cstdint>

#define N_NODES 100000
#define N_EDGES 1600000
#define DIN 48
#define DOUT 128
#define OUT_ELEMS (N_NODES * DOUT)                     // 12,800,000
#define FULL_OUT  (OUT_ELEMS + 3 * N_EDGES + N_NODES)  // 17,700,000

#define SCAN_BLOCKS ((N_NODES + 1023) / 1024)          // 98

// Scratch node-feature buffers — written fully by gather, no zeroing.
__device__ float g_bufA[(size_t)N_NODES * DIN];
__device__ float g_bufB[(size_t)N_NODES * DIN];

// CSR-by-destination structures.
__device__ int    g_off[N_NODES + 1];
__device__ int    g_cursor[N_NODES];
__device__ int    g_bsum[SCAN_BLOCKS];
__device__ int    g_scan_ctr;              // zero-init; reset by last block
__device__ float2 g_epay[N_EDGES];         // {src_as_float_bits, dfs}

// Pre-split tf32 weights (hi/lo).
__device__ uint32_t g_W1h[48 * 128], g_W1l[48 * 128];
__device__ uint32_t g_W2h[128 * 128], g_W2l[128 * 128];

// ---------------------------------------------------------------------------
// tf32 helpers.
// ---------------------------------------------------------------------------
__device__ __forceinline__ void split_tf32(float x, uint32_t& hi, uint32_t& lo)
{
    float h, l;
    asm("cvt.rna.tf32.f32 %0, %1;" : "=f"(h) : "f"(x));
    float r = x - h;
    asm("cvt.rna.tf32.f32 %0, %1;" : "=f"(l) : "f"(r));
    hi = __float_as_uint(h);
    lo = __float_as_uint(l);
}

__device__ __forceinline__ void mma_tf32(float d[4],
                                         uint32_t a0, uint32_t a1, uint32_t a2, uint32_t a3,
                                         uint32_t b0, uint32_t b1)
{
    asm volatile("mma.sync.aligned.m16n8k8.row.col.f32.tf32.tf32.f32 "
                 "{%0,%1,%2,%3}, {%4,%5,%6,%7}, {%8,%9}, {%0,%1,%2,%3};"
                 : "+f"(d[0]), "+f"(d[1]), "+f"(d[2]), "+f"(d[3])
                 : "r"(a0), "r"(a1), "r"(a2), "r"(a3), "r"(b0), "r"(b1));
}

// ---------------------------------------------------------------------------
// hist (x4 edges/thread, return-less atomics) + weight split fused.
// ---------------------------------------------------------------------------
#define HB  ((N_EDGES / 4 + 255) / 256)     // 1563
#define WB  64                              // 16384 / 256

__global__ void hist_and_split(const int* __restrict__ en,
                               const float* __restrict__ W1, const float* __restrict__ W2)
{
    if (blockIdx.x < HB) {
        int e0 = (blockIdx.x * blockDim.x + threadIdx.x) * 4;
        if (e0 + 4 <= N_EDGES) {
            int4 d4 = *(const int4*)(en + e0);
            atomicAdd(&g_off[d4.x], 1);
            atomicAdd(&g_off[d4.y], 1);
            atomicAdd(&g_off[d4.z], 1);
            atomicAdd(&g_off[d4.w], 1);
        } else {
            for (int e = e0; e < N_EDGES; e++)
                atomicAdd(&g_off[__ldg(en + e)], 1);
        }
    } else {
        int i = (blockIdx.x - HB) * blockDim.x + threadIdx.x;
        if (i < 48 * 128)  split_tf32(__ldg(W1 + i), g_W1h[i], g_W1l[i]);
        if (i < 128 * 128) split_tf32(__ldg(W2 + i), g_W2h[i], g_W2l[i]);
    }
}

// ---------------------------------------------------------------------------
// scanA+scanB fused (last-block-arrival pattern).
// ---------------------------------------------------------------------------
__global__ void scanAB()
{
    __shared__ int sh[256];
    __shared__ bool is_last;
    int tid = threadIdx.x;
    int base = blockIdx.x * 1024 + tid * 4;
    int s = 0;
    #pragma unroll
    for (int j = 0; j < 4; j++)
        s += (base + j < N_NODES) ? g_off[base + j] : 0;
    sh[tid] = s;
    __syncthreads();
    for (int d = 128; d > 0; d >>= 1) {
        if (tid < d) sh[tid] += sh[tid + d];
        __syncthreads();
    }
    if (tid == 0) {
        g_bsum[blockIdx.x] = sh[0];
        __threadfence();
        int c = atomicAdd(&g_scan_ctr, 1);
        is_last = (c == gridDim.x - 1);
    }
    __syncthreads();
    if (!is_last) return;

    int v = (tid < SCAN_BLOCKS) ? __ldcg(&g_bsum[tid]) : 0;
    __syncthreads();
    sh[tid] = v;
    __syncthreads();
    for (int d = 1; d < 256; d <<= 1) {
        int x = (tid >= d) ? sh[tid - d] : 0;
        __syncthreads();
        sh[tid] += x;
        __syncthreads();
    }
    if (tid < SCAN_BLOCKS) g_bsum[tid] = sh[tid] - v;
    if (tid == 0) { g_off[N_NODES] = sh[255]; g_scan_ctr = 0; }
}

// ---------------------------------------------------------------------------
// Phase C: block-local exclusive scan + block prefix; offsets & cursors.
// TAIL: also echoes df into the output (coalesced DRAM STG, free here).
// ---------------------------------------------------------------------------
template <bool TAIL>
__global__ void scanC(const float* __restrict__ df, float* __restrict__ out)
{
    __shared__ int sh[256];
    int tid = threadIdx.x;
    int base = blockIdx.x * 1024 + tid * 4;
    int v[4];
    int s = 0;
    #pragma unroll
    for (int j = 0; j < 4; j++) {
        v[j] = (base + j < N_NODES) ? g_off[base + j] : 0;
        s += v[j];
    }
    sh[tid] = s;
    __syncthreads();
    for (int d = 1; d < 256; d <<= 1) {
        int x = (tid >= d) ? sh[tid - d] : 0;
        __syncthreads();
        sh[tid] += x;
        __syncthreads();
    }
    int ex = sh[tid] - s + g_bsum[blockIdx.x];
    #pragma unroll
    for (int j = 0; j < 4; j++) {
        if (base + j < N_NODES) {
            g_off[base + j]    = ex;
            g_cursor[base + j] = ex;
            if (TAIL)
                out[OUT_ELEMS + 3 * N_EDGES + base + j] = __ldg(df + base + j);
        }
        ex += v[j];
    }
}

// ---------------------------------------------------------------------------
// fill: ONE edge per thread (max TLP on the atomic-return chain).
// TAIL: echoes sn/en/dfs as coalesced scalar stores.
// ---------------------------------------------------------------------------
#define EB ((N_EDGES + 255) / 256)          // 6250

template <bool TAIL>
__global__ void fill_kernel(const int* __restrict__ sn, const int* __restrict__ en,
                            const float* __restrict__ dfs, float* __restrict__ out)
{
    int e = blockIdx.x * blockDim.x + threadIdx.x;
    if (e >= N_EDGES) return;
    int s = __ldg(sn + e);
    int d = __ldg(en + e);
    float f = __ldg(dfs + e);
    int pos = atomicAdd(&g_cursor[d], 1);
    g_epay[pos] = make_float2(__int_as_float(s), f);
    if (TAIL) {
        float* p = out + OUT_ELEMS;
        p[e]               = (float)s;
        p[N_EDGES + e]     = (float)d;
        p[2 * N_EDGES + e] = f;
    }
}

// ---------------------------------------------------------------------------
// Gather pass: dst[n] = df[n] * sum_{e: end=n} src[start_e] * dfs_e
// 12 threads per node, one float4 chunk each, unrolled x4.
// ---------------------------------------------------------------------------
#define GB ((N_NODES * 12 + 255) / 256)     // 4688

__global__ void gather_pass(const float* __restrict__ src, float* __restrict__ dst,
                            const float* __restrict__ df)
{
    int t = blockIdx.x * blockDim.x + threadIdx.x;
    if (t >= N_NODES * 12) return;
    int n = t / 12;
    int q = t - n * 12;

    int o0 = __ldg(&g_off[n]);
    int o1 = __ldg(&g_off[n + 1]);

    float4 acc = make_float4(0.f, 0.f, 0.f, 0.f);
    int i = o0;
    for (; i + 4 <= o1; i += 4) {
        float2 p0 = __ldg(&g_epay[i]);
        float2 p1 = __ldg(&g_epay[i + 1]);
        float2 p2 = __ldg(&g_epay[i + 2]);
        float2 p3 = __ldg(&g_epay[i + 3]);
        float4 v0 = __ldg((const float4*)(src + (size_t)__float_as_int(p0.x) * DIN) + q);
        float4 v1 = __ldg((const float4*)(src + (size_t)__float_as_int(p1.x) * DIN) + q);
        float4 v2 = __ldg((const float4*)(src + (size_t)__float_as_int(p2.x) * DIN) + q);
        float4 v3 = __ldg((const float4*)(src + (size_t)__float_as_int(p3.x) * DIN) + q);
        acc.x = fmaf(v0.x, p0.y, acc.x); acc.y = fmaf(v0.y, p0.y, acc.y);
        acc.z = fmaf(v0.z, p0.y, acc.z); acc.w = fmaf(v0.w, p0.y, acc.w);
        acc.x = fmaf(v1.x, p1.y, acc.x); acc.y = fmaf(v1.y, p1.y, acc.y);
        acc.z = fmaf(v1.z, p1.y, acc.z); acc.w = fmaf(v1.w, p1.y, acc.w);
        acc.x = fmaf(v2.x, p2.y, acc.x); acc.y = fmaf(v2.y, p2.y, acc.y);
        acc.z = fmaf(v2.z, p2.y, acc.z); acc.w = fmaf(v2.w, p2.y, acc.w);
        acc.x = fmaf(v3.x, p3.y, acc.x); acc.y = fmaf(v3.y, p3.y, acc.y);
        acc.z = fmaf(v3.z, p3.y, acc.z); acc.w = fmaf(v3.w, p3.y, acc.w);
    }
    for (; i < o1; i++) {
        float2 p = __ldg(&g_epay[i]);
        float4 v = __ldg((const float4*)(src + (size_t)__float_as_int(p.x) * DIN) + q);
        acc.x = fmaf(v.x, p.y, acc.x); acc.y = fmaf(v.y, p.y, acc.y);
        acc.z = fmaf(v.z, p.y, acc.z); acc.w = fmaf(v.w, p.y, acc.w);
    }

    float f = __ldg(df + n);
    acc.x *= f; acc.y *= f; acc.z *= f; acc.w *= f;
    ((float4*)(dst + (size_t)n * DIN))[q] = acc;
}

// ---------------------------------------------------------------------------
// Persistent fused MLP on tensor cores (tf32 mma.sync, 3xTF32 compensation):
//   out = relu(x @ W1 + b1) @ W2 + b2
// 384 threads/CTA = 12 warps/SM (3/SMSP). Reg budget 64k/384 = 170/thread so
// the ~140-reg working set (d2[64]+h[32]+temps) fits WITHOUT spills (the 512-
// thread R11 variant was capped at 128 regs -> local-memory spills in the hot
// loop). Each warp owns a 16-node group end-to-end, grid-striding; smem holds
// only the pre-split weights. Arithmetic identical to R11 (bit-same output).
// ---------------------------------------------------------------------------
#define MLP_THREADS 384
#define MLP_GRID 148
#define MLP_WARPS (MLP_GRID * (MLP_THREADS / 32))      // 1776
#define N_GROUPS ((N_NODES + 15) / 16)                 // 6250
#define W_STRIDE 136
#define MLP_SMEM_WORDS (48*W_STRIDE*2 + 128*W_STRIDE*2 + 256)   // 48128 words

__global__ void __launch_bounds__(MLP_THREADS, 1)
mlp_kernel(const float* __restrict__ x,
           const float* __restrict__ b1, const float* __restrict__ b2,
           float* __restrict__ out)
{
    extern __shared__ uint32_t smu[];
    uint32_t* W1hs = smu;                         // [48][136]
    uint32_t* W1ls = W1hs + 48 * W_STRIDE;
    uint32_t* W2hs = W1ls + 48 * W_STRIDE;        // [128][136]
    uint32_t* W2ls = W2hs + 128 * W_STRIDE;
    float*    b1s  = (float*)(W2ls + 128 * W_STRIDE);
    float*    b2s  = b1s + 128;

    int tid = threadIdx.x;

    for (int i = tid; i < 48 * 128; i += MLP_THREADS) {
        int k = i >> 7, n = i & 127;
        W1hs[k * W_STRIDE + n] = g_W1h[i];
        W1ls[k * W_STRIDE + n] = g_W1l[i];
    }
    for (int i = tid; i < 128 * 128; i += MLP_THREADS) {
        int k = i >> 7, n = i & 127;
        W2hs[k * W_STRIDE + n] = g_W2h[i];
        W2ls[k * W_STRIDE + n] = g_W2l[i];
    }
    if (tid < 128) { b1s[tid] = __ldg(b1 + tid); b2s[tid] = __ldg(b2 + tid); }
    __syncthreads();

    int warp = tid >> 5;
    int lane = tid & 31;
    int r = lane >> 2;
    int c = lane & 3;
    int srcA = (lane & ~3) | (c >> 1);
    int srcB = srcA + 2;
    bool odd = (c & 1);

    for (int g = blockIdx.x * (MLP_THREADS / 32) + warp; g < N_GROUPS; g += MLP_WARPS) {
        int node0 = g * 16;
        int row0 = node0 + r;
        int row1 = row0 + 8;
        bool ok0 = row0 < N_NODES;
        bool ok1 = row1 < N_NODES;
        const float* y0 = x + (size_t)row0 * DIN;
        const float* y1 = x + (size_t)row1 * DIN;

        float d2[16][4];
        #pragma unroll
        for (int nt = 0; nt < 16; nt++) {
            d2[nt][0] = b2s[nt * 8 + 2 * c];
            d2[nt][1] = b2s[nt * 8 + 2 * c + 1];
            d2[nt][2] = d2[nt][0];
            d2[nt][3] = d2[nt][1];
        }

        #pragma unroll
        for (int half = 0; half < 2; half++) {
            // ---- stage 1 (half): H[:, half*64 .. half*64+63] ----
            float h[8][4];
            #pragma unroll
            for (int nt = 0; nt < 8; nt++) {
                int n0 = half * 64 + nt * 8;
                h[nt][0] = b1s[n0 + 2 * c];
                h[nt][1] = b1s[n0 + 2 * c + 1];
                h[nt][2] = h[nt][0];
                h[nt][3] = h[nt][1];
            }
            #pragma unroll
            for (int ks = 0; ks < 6; ks++) {
                int k0 = ks * 8;
                float a0 = ok0 ? __ldg(y0 + k0 + c)     : 0.f;
                float a1 = ok1 ? __ldg(y1 + k0 + c)     : 0.f;
                float a2 = ok0 ? __ldg(y0 + k0 + c + 4) : 0.f;
                float a3 = ok1 ? __ldg(y1 + k0 + c + 4) : 0.f;
                uint32_t ah[4], al[4];
                split_tf32(a0, ah[0], al[0]);
                split_tf32(a1, ah[1], al[1]);
                split_tf32(a2, ah[2], al[2]);
                split_tf32(a3, ah[3], al[3]);
                #pragma unroll
                for (int nt = 0; nt < 8; nt++) {
                    int ncol = half * 64 + nt * 8 + r;
                    uint32_t bh0 = W1hs[(k0 + c) * W_STRIDE + ncol];
                    uint32_t bh1 = W1hs[(k0 + c + 4) * W_STRIDE + ncol];
                    uint32_t bl0 = W1ls[(k0 + c) * W_STRIDE + ncol];
                    uint32_t bl1 = W1ls[(k0 + c + 4) * W_STRIDE + ncol];
                    mma_tf32(h[nt], ah[0], ah[1], ah[2], ah[3], bh0, bh1);
                    mma_tf32(h[nt], al[0], al[1], al[2], al[3], bh0, bh1);
                    mma_tf32(h[nt], ah[0], ah[1], ah[2], ah[3], bl0, bl1);
                }
            }
            #pragma unroll
            for (int nt = 0; nt < 8; nt++) {
                h[nt][0] = fmaxf(h[nt][0], 0.f);
                h[nt][1] = fmaxf(h[nt][1], 0.f);
                h[nt][2] = fmaxf(h[nt][2], 0.f);
                h[nt][3] = fmaxf(h[nt][3], 0.f);
            }

            // ---- stage 2 partial: d2 += H[:, k0..k0+7] @ W2[k0..k0+7, :] ----
            #pragma unroll
            for (int ks2 = 0; ks2 < 8; ks2++) {
                int k0 = half * 64 + ks2 * 8;
                float w0 = __shfl_sync(0xFFFFFFFFu, h[ks2][0], srcA);
                float w1 = __shfl_sync(0xFFFFFFFFu, h[ks2][1], srcA);
                float w2 = __shfl_sync(0xFFFFFFFFu, h[ks2][2], srcA);
                float w3 = __shfl_sync(0xFFFFFFFFu, h[ks2][3], srcA);
                float x0 = __shfl_sync(0xFFFFFFFFu, h[ks2][0], srcB);
                float x1 = __shfl_sync(0xFFFFFFFFu, h[ks2][1], srcB);
                float x2 = __shfl_sync(0xFFFFFFFFu, h[ks2][2], srcB);
                float x3 = __shfl_sync(0xFFFFFFFFu, h[ks2][3], srcB);
                uint32_t ah[4], al[4];
                split_tf32(odd ? w1 : w0, ah[0], al[0]);
                split_tf32(odd ? w3 : w2, ah[1], al[1]);
                split_tf32(odd ? x1 : x0, ah[2], al[2]);
                split_tf32(odd ? x3 : x2, ah[3], al[3]);
                #pragma unroll
                for (int nt = 0; nt < 16; nt++) {
                    uint32_t bh0 = W2hs[(k0 + c) * W_STRIDE + nt * 8 + r];
                    uint32_t bh1 = W2hs[(k0 + c + 4) * W_STRIDE + nt * 8 + r];
                    uint32_t bl0 = W2ls[(k0 + c) * W_STRIDE + nt * 8 + r];
                    uint32_t bl1 = W2ls[(k0 + c + 4) * W_STRIDE + nt * 8 + r];
                    mma_tf32(d2[nt], ah[0], ah[1], ah[2], ah[3], bh0, bh1);
                    mma_tf32(d2[nt], al[0], al[1], al[2], al[3], bh0, bh1);
                    mma_tf32(d2[nt], ah[0], ah[1], ah[2], ah[3], bl0, bl1);
                }
            }
        }

        // ---- store ----
        #pragma unroll
        for (int nt = 0; nt < 16; nt++) {
            if (ok0)
                *(float2*)(out + (size_t)row0 * 128 + nt * 8 + 2 * c) =
                    make_float2(d2[nt][0], d2[nt][1]);
            if (ok1)
                *(float2*)(out + (size_t)row1 * 128 + nt * 8 + 2 * c) =
                    make_float2(d2[nt][2], d2[nt][3]);
        }
    }
}

extern "C" void kernel_launch(void* const* d_in, const int* in_sizes, int n_in,
                              void* d_out, int out_size)
{
    const float* y   = (const float*)d_in[0];
    const int*   sn  = (const int*)  d_in[1];
    const int*   en  = (const int*)  d_in[2];
    const float* dfs = (const float*)d_in[3];
    const float* df  = (const float*)d_in[4];
    const float* W1  = (const float*)d_in[5];
    const float* b1  = (const float*)d_in[6];
    const float* W2  = (const float*)d_in[7];
    const float* b2  = (const float*)d_in[8];
    float* out = (float*)d_out;

    float *bufA, *bufB;
    cudaGetSymbolAddress((void**)&bufA, g_bufA);
    cudaGetSymbolAddress((void**)&bufB, g_bufB);
    int* offp;
    cudaGetSymbolAddress((void**)&offp, g_off);

    cudaFuncSetAttribute(mlp_kernel, cudaFuncAttributeMaxDynamicSharedMemorySize,
                         MLP_SMEM_WORDS * (int)sizeof(uint32_t));

    const bool tail = (out_size >= FULL_OUT);

    // ---- CSR build (by destination), weight split + echoes overlapped ----
    cudaMemsetAsync(offp, 0, N_NODES * sizeof(int));
    hist_and_split<<<HB + WB, 256>>>(en, W1, W2);
    scanAB<<<SCAN_BLOCKS, 256>>>();
    if (tail) {
        scanC<true><<<SCAN_BLOCKS, 256>>>(df, out);
        fill_kernel<true><<<EB, 256>>>(sn, en, dfs, out);
    } else {
        scanC<false><<<SCAN_BLOCKS, 256>>>(df, out);
        fill_kernel<false><<<EB, 256>>>(sn, en, dfs, out);
    }

    // ---- two gather passes ----
    gather_pass<<<GB, 256>>>(y,    bufA, df);
    gather_pass<<<GB, 256>>>(bufA, bufB, df);

    // ---- persistent fused tensor-core MLP (12 warps/SM, no spills) ----
    mlp_kernel<<<MLP_GRID, MLP_THREADS,
                 MLP_SMEM_WORDS * sizeof(uint32_t)>>>(bufB, b1, b2, out);
}

// round 13
// speedup vs baseline: 1.2645x; 1.1359x over previous
#include <cuda_runtime.h>
#include <cstdint>

#define N_NODES 100000
#define N_EDGES 1600000
#define DIN 48
#define DOUT 128
#define OUT_ELEMS (N_NODES * DOUT)                     // 12,800,000
#define FULL_OUT  (OUT_ELEMS + 3 * N_EDGES + N_NODES)  // 17,700,000

#define SCAN_BLOCKS ((N_NODES + 1023) / 1024)          // 98

// Scratch node-feature buffers — written fully by gather, no zeroing.
__device__ float g_bufA[(size_t)N_NODES * DIN];
__device__ float g_bufB[(size_t)N_NODES * DIN];

// CSR-by-destination structures.
__device__ int    g_off[N_NODES + 1];
__device__ int    g_cursor[N_NODES];
__device__ int    g_bsum[SCAN_BLOCKS];
__device__ int    g_scan_ctr;              // zero-init; reset by last block
__device__ float2 g_epay[N_EDGES];         // {src_as_float_bits, dfs}

// Pre-split tf32 weights (hi/lo).
__device__ uint32_t g_W1h[48 * 128];
__device__ uint32_t g_W2h[128 * 128];

// ---------------------------------------------------------------------------
// tf32 helpers.
// ---------------------------------------------------------------------------
__device__ __forceinline__ void split_tf32(float x, uint32_t& hi, uint32_t& lo)
{
    float h, l;
    asm("cvt.rna.tf32.f32 %0, %1;" : "=f"(h) : "f"(x));
    float r = x - h;
    asm("cvt.rna.tf32.f32 %0, %1;" : "=f"(l) : "f"(r));
    hi = __float_as_uint(h);
    lo = __float_as_uint(l);
}

__device__ __forceinline__ uint32_t cvt_tf32(float x)
{
    float h;
    asm("cvt.rna.tf32.f32 %0, %1;" : "=f"(h) : "f"(x));
    return __float_as_uint(h);
}

__device__ __forceinline__ void mma_tf32(float d[4],
                                         uint32_t a0, uint32_t a1, uint32_t a2, uint32_t a3,
                                         uint32_t b0, uint32_t b1)
{
    asm volatile("mma.sync.aligned.m16n8k8.row.col.f32.tf32.tf32.f32 "
                 "{%0,%1,%2,%3}, {%4,%5,%6,%7}, {%8,%9}, {%0,%1,%2,%3};"
                 : "+f"(d[0]), "+f"(d[1]), "+f"(d[2]), "+f"(d[3])
                 : "r"(a0), "r"(a1), "r"(a2), "r"(a3), "r"(b0), "r"(b1));
}

// ---------------------------------------------------------------------------
// hist (x4 edges/thread, return-less atomics) + weight hi-split fused.
// ---------------------------------------------------------------------------
#define HB  ((N_EDGES / 4 + 255) / 256)     // 1563
#define WB  64                              // 16384 / 256

__global__ void hist_and_split(const int* __restrict__ en,
                               const float* __restrict__ W1, const float* __restrict__ W2)
{
    if (blockIdx.x < HB) {
        int e0 = (blockIdx.x * blockDim.x + threadIdx.x) * 4;
        if (e0 + 4 <= N_EDGES) {
            int4 d4 = *(const int4*)(en + e0);
            atomicAdd(&g_off[d4.x], 1);
            atomicAdd(&g_off[d4.y], 1);
            atomicAdd(&g_off[d4.z], 1);
            atomicAdd(&g_off[d4.w], 1);
        } else {
            for (int e = e0; e < N_EDGES; e++)
                atomicAdd(&g_off[__ldg(en + e)], 1);
        }
    } else {
        int i = (blockIdx.x - HB) * blockDim.x + threadIdx.x;
        if (i < 48 * 128)  g_W1h[i] = cvt_tf32(__ldg(W1 + i));
        if (i < 128 * 128) g_W2h[i] = cvt_tf32(__ldg(W2 + i));
    }
}

// ---------------------------------------------------------------------------
// scanA+scanB fused (last-block-arrival pattern).
// ---------------------------------------------------------------------------
__global__ void scanAB()
{
    __shared__ int sh[256];
    __shared__ bool is_last;
    int tid = threadIdx.x;
    int base = blockIdx.x * 1024 + tid * 4;
    int s = 0;
    #pragma unroll
    for (int j = 0; j < 4; j++)
        s += (base + j < N_NODES) ? g_off[base + j] : 0;
    sh[tid] = s;
    __syncthreads();
    for (int d = 128; d > 0; d >>= 1) {
        if (tid < d) sh[tid] += sh[tid + d];
        __syncthreads();
    }
    if (tid == 0) {
        g_bsum[blockIdx.x] = sh[0];
        __threadfence();
        int c = atomicAdd(&g_scan_ctr, 1);
        is_last = (c == gridDim.x - 1);
    }
    __syncthreads();
    if (!is_last) return;

    int v = (tid < SCAN_BLOCKS) ? __ldcg(&g_bsum[tid]) : 0;
    __syncthreads();
    sh[tid] = v;
    __syncthreads();
    for (int d = 1; d < 256; d <<= 1) {
        int x = (tid >= d) ? sh[tid - d] : 0;
        __syncthreads();
        sh[tid] += x;
        __syncthreads();
    }
    if (tid < SCAN_BLOCKS) g_bsum[tid] = sh[tid] - v;
    if (tid == 0) { g_off[N_NODES] = sh[255]; g_scan_ctr = 0; }
}

// ---------------------------------------------------------------------------
// Phase C: block-local exclusive scan + block prefix; offsets & cursors.
// TAIL: also echoes df into the output (coalesced DRAM STG, free here).
// ---------------------------------------------------------------------------
template <bool TAIL>
__global__ void scanC(const float* __restrict__ df, float* __restrict__ out)
{
    __shared__ int sh[256];
    int tid = threadIdx.x;
    int base = blockIdx.x * 1024 + tid * 4;
    int v[4];
    int s = 0;
    #pragma unroll
    for (int j = 0; j < 4; j++) {
        v[j] = (base + j < N_NODES) ? g_off[base + j] : 0;
        s += v[j];
    }
    sh[tid] = s;
    __syncthreads();
    for (int d = 1; d < 256; d <<= 1) {
        int x = (tid >= d) ? sh[tid - d] : 0;
        __syncthreads();
        sh[tid] += x;
        __syncthreads();
    }
    int ex = sh[tid] - s + g_bsum[blockIdx.x];
    #pragma unroll
    for (int j = 0; j < 4; j++) {
        if (base + j < N_NODES) {
            g_off[base + j]    = ex;
            g_cursor[base + j] = ex;
            if (TAIL)
                out[OUT_ELEMS + 3 * N_EDGES + base + j] = __ldg(df + base + j);
        }
        ex += v[j];
    }
}

// ---------------------------------------------------------------------------
// fill: ONE edge per thread (max TLP on the atomic-return chain).
// TAIL: echoes sn/en/dfs as coalesced scalar stores.
// ---------------------------------------------------------------------------
#define EB ((N_EDGES + 255) / 256)          // 6250

template <bool TAIL>
__global__ void fill_kernel(const int* __restrict__ sn, const int* __restrict__ en,
                            const float* __restrict__ dfs, float* __restrict__ out)
{
    int e = blockIdx.x * blockDim.x + threadIdx.x;
    if (e >= N_EDGES) return;
    int s = __ldg(sn + e);
    int d = __ldg(en + e);
    float f = __ldg(dfs + e);
    int pos = atomicAdd(&g_cursor[d], 1);
    g_epay[pos] = make_float2(__int_as_float(s), f);
    if (TAIL) {
        float* p = out + OUT_ELEMS;
        p[e]               = (float)s;
        p[N_EDGES + e]     = (float)d;
        p[2 * N_EDGES + e] = f;
    }
}

// ---------------------------------------------------------------------------
// Gather pass: dst[n] = df[n] * sum_{e: end=n} src[start_e] * dfs_e
// 12 threads per node, one float4 chunk each, unrolled x4.
// ---------------------------------------------------------------------------
#define GB ((N_NODES * 12 + 255) / 256)     // 4688

__global__ void gather_pass(const float* __restrict__ src, float* __restrict__ dst,
                            const float* __restrict__ df)
{
    int t = blockIdx.x * blockDim.x + threadIdx.x;
    if (t >= N_NODES * 12) return;
    int n = t / 12;
    int q = t - n * 12;

    int o0 = __ldg(&g_off[n]);
    int o1 = __ldg(&g_off[n + 1]);

    float4 acc = make_float4(0.f, 0.f, 0.f, 0.f);
    int i = o0;
    for (; i + 4 <= o1; i += 4) {
        float2 p0 = __ldg(&g_epay[i]);
        float2 p1 = __ldg(&g_epay[i + 1]);
        float2 p2 = __ldg(&g_epay[i + 2]);
        float2 p3 = __ldg(&g_epay[i + 3]);
        float4 v0 = __ldg((const float4*)(src + (size_t)__float_as_int(p0.x) * DIN) + q);
        float4 v1 = __ldg((const float4*)(src + (size_t)__float_as_int(p1.x) * DIN) + q);
        float4 v2 = __ldg((const float4*)(src + (size_t)__float_as_int(p2.x) * DIN) + q);
        float4 v3 = __ldg((const float4*)(src + (size_t)__float_as_int(p3.x) * DIN) + q);
        acc.x = fmaf(v0.x, p0.y, acc.x); acc.y = fmaf(v0.y, p0.y, acc.y);
        acc.z = fmaf(v0.z, p0.y, acc.z); acc.w = fmaf(v0.w, p0.y, acc.w);
        acc.x = fmaf(v1.x, p1.y, acc.x); acc.y = fmaf(v1.y, p1.y, acc.y);
        acc.z = fmaf(v1.z, p1.y, acc.z); acc.w = fmaf(v1.w, p1.y, acc.w);
        acc.x = fmaf(v2.x, p2.y, acc.x); acc.y = fmaf(v2.y, p2.y, acc.y);
        acc.z = fmaf(v2.z, p2.y, acc.z); acc.w = fmaf(v2.w, p2.y, acc.w);
        acc.x = fmaf(v3.x, p3.y, acc.x); acc.y = fmaf(v3.y, p3.y, acc.y);
        acc.z = fmaf(v3.z, p3.y, acc.z); acc.w = fmaf(v3.w, p3.y, acc.w);
    }
    for (; i < o1; i++) {
        float2 p = __ldg(&g_epay[i]);
        float4 v = __ldg((const float4*)(src + (size_t)__float_as_int(p.x) * DIN) + q);
        acc.x = fmaf(v.x, p.y, acc.x); acc.y = fmaf(v.y, p.y, acc.y);
        acc.z = fmaf(v.z, p.y, acc.z); acc.w = fmaf(v.w, p.y, acc.w);
    }

    float f = __ldg(df + n);
    acc.x *= f; acc.y *= f; acc.z *= f; acc.w *= f;
    ((float4*)(dst + (size_t)n * DIN))[q] = acc;
}

// ---------------------------------------------------------------------------
// Persistent fused MLP on tensor cores (2xTF32: hi*hi + lo*hi; the hi*lo
// term is dropped — bound ≤2.4e-4 rel, ~4x under the 1e-3 threshold):
//   out = relu(x @ W1 + b1) @ W2 + b2
// 384 threads/CTA = 12 warps/SM. Per nt-step: 2 LDS + 2 MMA (was 4+3).
// Weight-lo arrays are gone entirely (smem 188KB -> 94KB).
// ---------------------------------------------------------------------------
#define MLP_THREADS 384
#define MLP_GRID 148
#define MLP_WARPS (MLP_GRID * (MLP_THREADS / 32))      // 1776
#define N_GROUPS ((N_NODES + 15) / 16)                 // 6250
#define W_STRIDE 136
#define MLP_SMEM_WORDS (48*W_STRIDE + 128*W_STRIDE + 256)   // 24192 words

__global__ void __launch_bounds__(MLP_THREADS, 1)
mlp_kernel(const float* __restrict__ x,
           const float* __restrict__ b1, const float* __restrict__ b2,
           float* __restrict__ out)
{
    extern __shared__ uint32_t smu[];
    uint32_t* W1hs = smu;                         // [48][136]
    uint32_t* W2hs = W1hs + 48 * W_STRIDE;        // [128][136]
    float*    b1s  = (float*)(W2hs + 128 * W_STRIDE);
    float*    b2s  = b1s + 128;

    int tid = threadIdx.x;

    for (int i = tid; i < 48 * 128; i += MLP_THREADS) {
        int k = i >> 7, n = i & 127;
        W1hs[k * W_STRIDE + n] = g_W1h[i];
    }
    for (int i = tid; i < 128 * 128; i += MLP_THREADS) {
        int k = i >> 7, n = i & 127;
        W2hs[k * W_STRIDE + n] = g_W2h[i];
    }
    if (tid < 128) { b1s[tid] = __ldg(b1 + tid); b2s[tid] = __ldg(b2 + tid); }
    __syncthreads();

    int warp = tid >> 5;
    int lane = tid & 31;
    int r = lane >> 2;
    int c = lane & 3;
    int srcA = (lane & ~3) | (c >> 1);
    int srcB = srcA + 2;
    bool odd = (c & 1);

    for (int g = blockIdx.x * (MLP_THREADS / 32) + warp; g < N_GROUPS; g += MLP_WARPS) {
        int node0 = g * 16;
        int row0 = node0 + r;
        int row1 = row0 + 8;
        bool ok0 = row0 < N_NODES;
        bool ok1 = row1 < N_NODES;
        const float* y0 = x + (size_t)row0 * DIN;
        const float* y1 = x + (size_t)row1 * DIN;

        float d2[16][4];
        #pragma unroll
        for (int nt = 0; nt < 16; nt++) {
            d2[nt][0] = b2s[nt * 8 + 2 * c];
            d2[nt][1] = b2s[nt * 8 + 2 * c + 1];
            d2[nt][2] = d2[nt][0];
            d2[nt][3] = d2[nt][1];
        }

        #pragma unroll
        for (int half = 0; half < 2; half++) {
            // ---- stage 1 (half): H[:, half*64 .. half*64+63] ----
            float h[8][4];
            #pragma unroll
            for (int nt = 0; nt < 8; nt++) {
                int n0 = half * 64 + nt * 8;
                h[nt][0] = b1s[n0 + 2 * c];
                h[nt][1] = b1s[n0 + 2 * c + 1];
                h[nt][2] = h[nt][0];
                h[nt][3] = h[nt][1];
            }
            #pragma unroll
            for (int ks = 0; ks < 6; ks++) {
                int k0 = ks * 8;
                float a0 = ok0 ? __ldg(y0 + k0 + c)     : 0.f;
                float a1 = ok1 ? __ldg(y1 + k0 + c)     : 0.f;
                float a2 = ok0 ? __ldg(y0 + k0 + c + 4) : 0.f;
                float a3 = ok1 ? __ldg(y1 + k0 + c + 4) : 0.f;
                uint32_t ah[4], al[4];
                split_tf32(a0, ah[0], al[0]);
                split_tf32(a1, ah[1], al[1]);
                split_tf32(a2, ah[2], al[2]);
                split_tf32(a3, ah[3], al[3]);
                #pragma unroll
                for (int nt = 0; nt < 8; nt++) {
                    int ncol = half * 64 + nt * 8 + r;
                    uint32_t bh0 = W1hs[(k0 + c) * W_STRIDE + ncol];
                    uint32_t bh1 = W1hs[(k0 + c + 4) * W_STRIDE + ncol];
                    mma_tf32(h[nt], ah[0], ah[1], ah[2], ah[3], bh0, bh1);   // hi*hi
                    mma_tf32(h[nt], al[0], al[1], al[2], al[3], bh0, bh1);   // lo*hi
                }
            }
            #pragma unroll
            for (int nt = 0; nt < 8; nt++) {
                h[nt][0] = fmaxf(h[nt][0], 0.f);
                h[nt][1] = fmaxf(h[nt][1], 0.f);
                h[nt][2] = fmaxf(h[nt][2], 0.f);
                h[nt][3] = fmaxf(h[nt][3], 0.f);
            }

            // ---- stage 2 partial: d2 += H[:, k0..k0+7] @ W2[k0..k0+7, :] ----
            #pragma unroll
            for (int ks2 = 0; ks2 < 8; ks2++) {
                int k0 = half * 64 + ks2 * 8;
                float w0 = __shfl_sync(0xFFFFFFFFu, h[ks2][0], srcA);
                float w1 = __shfl_sync(0xFFFFFFFFu, h[ks2][1], srcA);
                float w2 = __shfl_sync(0xFFFFFFFFu, h[ks2][2], srcA);
                float w3 = __shfl_sync(0xFFFFFFFFu, h[ks2][3], srcA);
                float x0 = __shfl_sync(0xFFFFFFFFu, h[ks2][0], srcB);
                float x1 = __shfl_sync(0xFFFFFFFFu, h[ks2][1], srcB);
                float x2 = __shfl_sync(0xFFFFFFFFu, h[ks2][2], srcB);
                float x3 = __shfl_sync(0xFFFFFFFFu, h[ks2][3], srcB);
                uint32_t ah[4], al[4];
                split_tf32(odd ? w1 : w0, ah[0], al[0]);
                split_tf32(odd ? w3 : w2, ah[1], al[1]);
                split_tf32(odd ? x1 : x0, ah[2], al[2]);
                split_tf32(odd ? x3 : x2, ah[3], al[3]);
                #pragma unroll
                for (int nt = 0; nt < 16; nt++) {
                    uint32_t bh0 = W2hs[(k0 + c) * W_STRIDE + nt * 8 + r];
                    uint32_t bh1 = W2hs[(k0 + c + 4) * W_STRIDE + nt * 8 + r];
                    mma_tf32(d2[nt], ah[0], ah[1], ah[2], ah[3], bh0, bh1);
                    mma_tf32(d2[nt], al[0], al[1], al[2], al[3], bh0, bh1);
                }
            }
        }

        // ---- store ----
        #pragma unroll
        for (int nt = 0; nt < 16; nt++) {
            if (ok0)
                *(float2*)(out + (size_t)row0 * 128 + nt * 8 + 2 * c) =
                    make_float2(d2[nt][0], d2[nt][1]);
            if (ok1)
                *(float2*)(out + (size_t)row1 * 128 + nt * 8 + 2 * c) =
                    make_float2(d2[nt][2], d2[nt][3]);
        }
    }
}

extern "C" void kernel_launch(void* const* d_in, const int* in_sizes, int n_in,
                              void* d_out, int out_size)
{
    const float* y   = (const float*)d_in[0];
    const int*   sn  = (const int*)  d_in[1];
    const int*   en  = (const int*)  d_in[2];
    const float* dfs = (const float*)d_in[3];
    const float* df  = (const float*)d_in[4];
    const float* W1  = (const float*)d_in[5];
    const float* b1  = (const float*)d_in[6];
    const float* W2  = (const float*)d_in[7];
    const float* b2  = (const float*)d_in[8];
    float* out = (float*)d_out;

    float *bufA, *bufB;
    cudaGetSymbolAddress((void**)&bufA, g_bufA);
    cudaGetSymbolAddress((void**)&bufB, g_bufB);
    int* offp;
    cudaGetSymbolAddress((void**)&offp, g_off);

    cudaFuncSetAttribute(mlp_kernel, cudaFuncAttributeMaxDynamicSharedMemorySize,
                         MLP_SMEM_WORDS * (int)sizeof(uint32_t));

    const bool tail = (out_size >= FULL_OUT);

    // ---- CSR build (by destination), weight split + echoes overlapped ----
    cudaMemsetAsync(offp, 0, N_NODES * sizeof(int));
    hist_and_split<<<HB + WB, 256>>>(en, W1, W2);
    scanAB<<<SCAN_BLOCKS, 256>>>();
    if (tail) {
        scanC<true><<<SCAN_BLOCKS, 256>>>(df, out);
        fill_kernel<true><<<EB, 256>>>(sn, en, dfs, out);
    } else {
        scanC<false><<<SCAN_BLOCKS, 256>>>(df, out);
        fill_kernel<false><<<EB, 256>>>(sn, en, dfs, out);
    }

    // ---- two gather passes ----
    gather_pass<<<GB, 256>>>(y,    bufA, df);
    gather_pass<<<GB, 256>>>(bufA, bufB, df);

    // ---- persistent fused tensor-core MLP (2xTF32) ----
    mlp_kernel<<<MLP_GRID, MLP_THREADS,
                 MLP_SMEM_WORDS * sizeof(uint32_t)>>>(bufB, b1, b2, out);
}

// round 14
// speedup vs baseline: 1.2964x; 1.0252x over previous
#include <cuda_runtime.h>
#include <cstdint>

#define N_NODES 100000
#define N_EDGES 1600000
#define DIN 48
#define DOUT 128
#define OUT_ELEMS (N_NODES * DOUT)                     // 12,800,000
#define FULL_OUT  (OUT_ELEMS + 3 * N_EDGES + N_NODES)  // 17,700,000

#define SCAN_BLOCKS ((N_NODES + 1023) / 1024)          // 98

// Scratch node-feature buffers — written fully by gather, no zeroing.
__device__ float g_bufA[(size_t)N_NODES * DIN];
__device__ float g_bufB[(size_t)N_NODES * DIN];

// CSR-by-destination structures.
__device__ int    g_off[N_NODES + 1];
__device__ int    g_rank[N_EDGES];         // rank of edge within its dest node
__device__ int    g_bsum[SCAN_BLOCKS];
__device__ int    g_scan_ctr;              // zero-init; reset by last block
__device__ int    g_mlp_ctr;               // work-stealing counter (reset by scanAB)
__device__ float2 g_epay[N_EDGES];         // {src_as_float_bits, dfs}

// Pre-split tf32 weights (hi only; 2xTF32 scheme).
__device__ uint32_t g_W1h[48 * 128];
__device__ uint32_t g_W2h[128 * 128];

// ---------------------------------------------------------------------------
// tf32 helpers.
// ---------------------------------------------------------------------------
__device__ __forceinline__ void split_tf32(float x, uint32_t& hi, uint32_t& lo)
{
    float h, l;
    asm("cvt.rna.tf32.f32 %0, %1;" : "=f"(h) : "f"(x));
    float r = x - h;
    asm("cvt.rna.tf32.f32 %0, %1;" : "=f"(l) : "f"(r));
    hi = __float_as_uint(h);
    lo = __float_as_uint(l);
}

__device__ __forceinline__ uint32_t cvt_tf32(float x)
{
    float h;
    asm("cvt.rna.tf32.f32 %0, %1;" : "=f"(h) : "f"(x));
    return __float_as_uint(h);
}

__device__ __forceinline__ void mma_tf32(float d[4],
                                         uint32_t a0, uint32_t a1, uint32_t a2, uint32_t a3,
                                         uint32_t b0, uint32_t b1)
{
    asm volatile("mma.sync.aligned.m16n8k8.row.col.f32.tf32.tf32.f32 "
                 "{%0,%1,%2,%3}, {%4,%5,%6,%7}, {%8,%9}, {%0,%1,%2,%3};"
                 : "+f"(d[0]), "+f"(d[1]), "+f"(d[2]), "+f"(d[3])
                 : "r"(a0), "r"(a1), "r"(a2), "r"(a3), "r"(b0), "r"(b1));
}

// ---------------------------------------------------------------------------
// hist (x4 edges/thread, RETURN atomics -> per-edge rank) + weight split.
// ---------------------------------------------------------------------------
#define HB  ((N_EDGES / 4 + 255) / 256)     // 1563
#define WB  64                              // 16384 / 256

__global__ void hist_and_split(const int* __restrict__ en,
                               const float* __restrict__ W1, const float* __restrict__ W2)
{
    if (blockIdx.x < HB) {
        int e0 = (blockIdx.x * blockDim.x + threadIdx.x) * 4;
        if (e0 + 4 <= N_EDGES) {
            int4 d4 = *(const int4*)(en + e0);
            int r0 = atomicAdd(&g_off[d4.x], 1);
            int r1 = atomicAdd(&g_off[d4.y], 1);
            int r2 = atomicAdd(&g_off[d4.z], 1);
            int r3 = atomicAdd(&g_off[d4.w], 1);
            *(int4*)(g_rank + e0) = make_int4(r0, r1, r2, r3);
        } else {
            for (int e = e0; e < N_EDGES; e++)
                g_rank[e] = atomicAdd(&g_off[__ldg(en + e)], 1);
        }
    } else {
        int i = (blockIdx.x - HB) * blockDim.x + threadIdx.x;
        if (i < 48 * 128)  g_W1h[i] = cvt_tf32(__ldg(W1 + i));
        if (i < 128 * 128) g_W2h[i] = cvt_tf32(__ldg(W2 + i));
    }
}

// ---------------------------------------------------------------------------
// scanA+scanB fused (last-block-arrival pattern). Also resets g_mlp_ctr.
// ---------------------------------------------------------------------------
__global__ void scanAB()
{
    __shared__ int sh[256];
    __shared__ bool is_last;
    int tid = threadIdx.x;
    int base = blockIdx.x * 1024 + tid * 4;
    int s = 0;
    #pragma unroll
    for (int j = 0; j < 4; j++)
        s += (base + j < N_NODES) ? g_off[base + j] : 0;
    sh[tid] = s;
    __syncthreads();
    for (int d = 128; d > 0; d >>= 1) {
        if (tid < d) sh[tid] += sh[tid + d];
        __syncthreads();
    }
    if (tid == 0) {
        g_bsum[blockIdx.x] = sh[0];
        __threadfence();
        int c = atomicAdd(&g_scan_ctr, 1);
        is_last = (c == gridDim.x - 1);
    }
    __syncthreads();
    if (!is_last) return;

    int v = (tid < SCAN_BLOCKS) ? __ldcg(&g_bsum[tid]) : 0;
    __syncthreads();
    sh[tid] = v;
    __syncthreads();
    for (int d = 1; d < 256; d <<= 1) {
        int x = (tid >= d) ? sh[tid - d] : 0;
        __syncthreads();
        sh[tid] += x;
        __syncthreads();
    }
    if (tid < SCAN_BLOCKS) g_bsum[tid] = sh[tid] - v;
    if (tid == 0) { g_off[N_NODES] = sh[255]; g_scan_ctr = 0; g_mlp_ctr = 0; }
}

// ---------------------------------------------------------------------------
// Phase C: block-local exclusive scan + block prefix; offsets (counts -> off).
// TAIL: also echoes df into the output (coalesced DRAM STG, free here).
// ---------------------------------------------------------------------------
template <bool TAIL>
__global__ void scanC(const float* __restrict__ df, float* __restrict__ out)
{
    __shared__ int sh[256];
    int tid = threadIdx.x;
    int base = blockIdx.x * 1024 + tid * 4;
    int v[4];
    int s = 0;
    #pragma unroll
    for (int j = 0; j < 4; j++) {
        v[j] = (base + j < N_NODES) ? g_off[base + j] : 0;
        s += v[j];
    }
    sh[tid] = s;
    __syncthreads();
    for (int d = 1; d < 256; d <<= 1) {
        int x = (tid >= d) ? sh[tid - d] : 0;
        __syncthreads();
        sh[tid] += x;
        __syncthreads();
    }
    int ex = sh[tid] - s + g_bsum[blockIdx.x];
    #pragma unroll
    for (int j = 0; j < 4; j++) {
        if (base + j < N_NODES) {
            g_off[base + j] = ex;
            if (TAIL)
                out[OUT_ELEMS + 3 * N_EDGES + base + j] = __ldg(df + base + j);
        }
        ex += v[j];
    }
}

// ---------------------------------------------------------------------------
// fill: ATOMIC-FREE. pos = off[en[e]] + rank[e]. Pure loads + one STG.
// TAIL: echoes sn/en/dfs as coalesced scalar stores.
// ---------------------------------------------------------------------------
#define EB ((N_EDGES + 255) / 256)          // 6250

template <bool TAIL>
__global__ void fill_kernel(const int* __restrict__ sn, const int* __restrict__ en,
                            const float* __restrict__ dfs, float* __restrict__ out)
{
    int e = blockIdx.x * blockDim.x + threadIdx.x;
    if (e >= N_EDGES) return;
    int s = __ldg(sn + e);
    int d = __ldg(en + e);
    float f = __ldg(dfs + e);
    int pos = __ldg(&g_off[d]) + __ldg(&g_rank[e]);
    g_epay[pos] = make_float2(__int_as_float(s), f);
    if (TAIL) {
        float* p = out + OUT_ELEMS;
        p[e]               = (float)s;
        p[N_EDGES + e]     = (float)d;
        p[2 * N_EDGES + e] = f;
    }
}

// ---------------------------------------------------------------------------
// Gather pass: dst[n] = df[n] * sum_{e: end=n} src[start_e] * dfs_e
// 12 threads per node, one float4 chunk each, unrolled x4.
// ---------------------------------------------------------------------------
#define GB ((N_NODES * 12 + 255) / 256)     // 4688

__global__ void gather_pass(const float* __restrict__ src, float* __restrict__ dst,
                            const float* __restrict__ df)
{
    int t = blockIdx.x * blockDim.x + threadIdx.x;
    if (t >= N_NODES * 12) return;
    int n = t / 12;
    int q = t - n * 12;

    int o0 = __ldg(&g_off[n]);
    int o1 = __ldg(&g_off[n + 1]);

    float4 acc = make_float4(0.f, 0.f, 0.f, 0.f);
    int i = o0;
    for (; i + 4 <= o1; i += 4) {
        float2 p0 = __ldg(&g_epay[i]);
        float2 p1 = __ldg(&g_epay[i + 1]);
        float2 p2 = __ldg(&g_epay[i + 2]);
        float2 p3 = __ldg(&g_epay[i + 3]);
        float4 v0 = __ldg((const float4*)(src + (size_t)__float_as_int(p0.x) * DIN) + q);
        float4 v1 = __ldg((const float4*)(src + (size_t)__float_as_int(p1.x) * DIN) + q);
        float4 v2 = __ldg((const float4*)(src + (size_t)__float_as_int(p2.x) * DIN) + q);
        float4 v3 = __ldg((const float4*)(src + (size_t)__float_as_int(p3.x) * DIN) + q);
        acc.x = fmaf(v0.x, p0.y, acc.x); acc.y = fmaf(v0.y, p0.y, acc.y);
        acc.z = fmaf(v0.z, p0.y, acc.z); acc.w = fmaf(v0.w, p0.y, acc.w);
        acc.x = fmaf(v1.x, p1.y, acc.x); acc.y = fmaf(v1.y, p1.y, acc.y);
        acc.z = fmaf(v1.z, p1.y, acc.z); acc.w = fmaf(v1.w, p1.y, acc.w);
        acc.x = fmaf(v2.x, p2.y, acc.x); acc.y = fmaf(v2.y, p2.y, acc.y);
        acc.z = fmaf(v2.z, p2.y, acc.z); acc.w = fmaf(v2.w, p2.y, acc.w);
        acc.x = fmaf(v3.x, p3.y, acc.x); acc.y = fmaf(v3.y, p3.y, acc.y);
        acc.z = fmaf(v3.z, p3.y, acc.z); acc.w = fmaf(v3.w, p3.y, acc.w);
    }
    for (; i < o1; i++) {
        float2 p = __ldg(&g_epay[i]);
        float4 v = __ldg((const float4*)(src + (size_t)__float_as_int(p.x) * DIN) + q);
        acc.x = fmaf(v.x, p.y, acc.x); acc.y = fmaf(v.y, p.y, acc.y);
        acc.z = fmaf(v.z, p.y, acc.z); acc.w = fmaf(v.w, p.y, acc.w);
    }

    float f = __ldg(df + n);
    acc.x *= f; acc.y *= f; acc.z *= f; acc.w *= f;
    ((float4*)(dst + (size_t)n * DIN))[q] = acc;
}

// ---------------------------------------------------------------------------
// Persistent fused MLP on tensor cores (2xTF32: hi*hi + lo*hi):
//   out = relu(x @ W1 + b1) @ W2 + b2
// 384 threads/CTA = 12 warps/SM. Dynamic work-stealing over 16-node groups
// (counter reset by scanAB each replay) removes the static-partition tail.
// ---------------------------------------------------------------------------
#define MLP_THREADS 384
#define MLP_GRID 148
#define N_GROUPS ((N_NODES + 15) / 16)                 // 6250
#define W_STRIDE 136
#define MLP_SMEM_WORDS (48*W_STRIDE + 128*W_STRIDE + 256)   // 24192 words

__global__ void __launch_bounds__(MLP_THREADS, 1)
mlp_kernel(const float* __restrict__ x,
           const float* __restrict__ b1, const float* __restrict__ b2,
           float* __restrict__ out)
{
    extern __shared__ uint32_t smu[];
    uint32_t* W1hs = smu;                         // [48][136]
    uint32_t* W2hs = W1hs + 48 * W_STRIDE;        // [128][136]
    float*    b1s  = (float*)(W2hs + 128 * W_STRIDE);
    float*    b2s  = b1s + 128;

    int tid = threadIdx.x;

    for (int i = tid; i < 48 * 128; i += MLP_THREADS) {
        int k = i >> 7, n = i & 127;
        W1hs[k * W_STRIDE + n] = g_W1h[i];
    }
    for (int i = tid; i < 128 * 128; i += MLP_THREADS) {
        int k = i >> 7, n = i & 127;
        W2hs[k * W_STRIDE + n] = g_W2h[i];
    }
    if (tid < 128) { b1s[tid] = __ldg(b1 + tid); b2s[tid] = __ldg(b2 + tid); }
    __syncthreads();

    int lane = tid & 31;
    int r = lane >> 2;
    int c = lane & 3;
    int srcA = (lane & ~3) | (c >> 1);
    int srcB = srcA + 2;
    bool odd = (c & 1);

    while (true) {
        int g = 0;
        if (lane == 0) g = atomicAdd(&g_mlp_ctr, 1);
        g = __shfl_sync(0xFFFFFFFFu, g, 0);
        if (g >= N_GROUPS) break;

        int node0 = g * 16;
        int row0 = node0 + r;
        int row1 = row0 + 8;
        bool ok0 = row0 < N_NODES;
        bool ok1 = row1 < N_NODES;
        const float* y0 = x + (size_t)row0 * DIN;
        const float* y1 = x + (size_t)row1 * DIN;

        float d2[16][4];
        #pragma unroll
        for (int nt = 0; nt < 16; nt++) {
            d2[nt][0] = b2s[nt * 8 + 2 * c];
            d2[nt][1] = b2s[nt * 8 + 2 * c + 1];
            d2[nt][2] = d2[nt][0];
            d2[nt][3] = d2[nt][1];
        }

        #pragma unroll
        for (int half = 0; half < 2; half++) {
            // ---- stage 1 (half): H[:, half*64 .. half*64+63] ----
            float h[8][4];
            #pragma unroll
            for (int nt = 0; nt < 8; nt++) {
                int n0 = half * 64 + nt * 8;
                h[nt][0] = b1s[n0 + 2 * c];
                h[nt][1] = b1s[n0 + 2 * c + 1];
                h[nt][2] = h[nt][0];
                h[nt][3] = h[nt][1];
            }
            #pragma unroll
            for (int ks = 0; ks < 6; ks++) {
                int k0 = ks * 8;
                float a0 = ok0 ? __ldg(y0 + k0 + c)     : 0.f;
                float a1 = ok1 ? __ldg(y1 + k0 + c)     : 0.f;
                float a2 = ok0 ? __ldg(y0 + k0 + c + 4) : 0.f;
                float a3 = ok1 ? __ldg(y1 + k0 + c + 4) : 0.f;
                uint32_t ah[4], al[4];
                split_tf32(a0, ah[0], al[0]);
                split_tf32(a1, ah[1], al[1]);
                split_tf32(a2, ah[2], al[2]);
                split_tf32(a3, ah[3], al[3]);
                #pragma unroll
                for (int nt = 0; nt < 8; nt++) {
                    int ncol = half * 64 + nt * 8 + r;
                    uint32_t bh0 = W1hs[(k0 + c) * W_STRIDE + ncol];
                    uint32_t bh1 = W1hs[(k0 + c + 4) * W_STRIDE + ncol];
                    mma_tf32(h[nt], ah[0], ah[1], ah[2], ah[3], bh0, bh1);   // hi*hi
                    mma_tf32(h[nt], al[0], al[1], al[2], al[3], bh0, bh1);   // lo*hi
                }
            }
            #pragma unroll
            for (int nt = 0; nt < 8; nt++) {
                h[nt][0] = fmaxf(h[nt][0], 0.f);
                h[nt][1] = fmaxf(h[nt][1], 0.f);
                h[nt][2] = fmaxf(h[nt][2], 0.f);
                h[nt][3] = fmaxf(h[nt][3], 0.f);
            }

            // ---- stage 2 partial: d2 += H[:, k0..k0+7] @ W2[k0..k0+7, :] ----
            #pragma unroll
            for (int ks2 = 0; ks2 < 8; ks2++) {
                int k0 = half * 64 + ks2 * 8;
                float w0 = __shfl_sync(0xFFFFFFFFu, h[ks2][0], srcA);
                float w1 = __shfl_sync(0xFFFFFFFFu, h[ks2][1], srcA);
                float w2 = __shfl_sync(0xFFFFFFFFu, h[ks2][2], srcA);
                float w3 = __shfl_sync(0xFFFFFFFFu, h[ks2][3], srcA);
                float x0 = __shfl_sync(0xFFFFFFFFu, h[ks2][0], srcB);
                float x1 = __shfl_sync(0xFFFFFFFFu, h[ks2][1], srcB);
                float x2 = __shfl_sync(0xFFFFFFFFu, h[ks2][2], srcB);
                float x3 = __shfl_sync(0xFFFFFFFFu, h[ks2][3], srcB);
                uint32_t ah[4], al[4];
                split_tf32(odd ? w1 : w0, ah[0], al[0]);
                split_tf32(odd ? w3 : w2, ah[1], al[1]);
                split_tf32(odd ? x1 : x0, ah[2], al[2]);
                split_tf32(odd ? x3 : x2, ah[3], al[3]);
                #pragma unroll
                for (int nt = 0; nt < 16; nt++) {
                    uint32_t bh0 = W2hs[(k0 + c) * W_STRIDE + nt * 8 + r];
                    uint32_t bh1 = W2hs[(k0 + c + 4) * W_STRIDE + nt * 8 + r];
                    mma_tf32(d2[nt], ah[0], ah[1], ah[2], ah[3], bh0, bh1);
                    mma_tf32(d2[nt], al[0], al[1], al[2], al[3], bh0, bh1);
                }
            }
        }

        // ---- store ----
        #pragma unroll
        for (int nt = 0; nt < 16; nt++) {
            if (ok0)
                *(float2*)(out + (size_t)row0 * 128 + nt * 8 + 2 * c) =
                    make_float2(d2[nt][0], d2[nt][1]);
            if (ok1)
                *(float2*)(out + (size_t)row1 * 128 + nt * 8 + 2 * c) =
                    make_float2(d2[nt][2], d2[nt][3]);
        }
    }
}

extern "C" void kernel_launch(void* const* d_in, const int* in_sizes, int n_in,
                              void* d_out, int out_size)
{
    const float* y   = (const float*)d_in[0];
    const int*   sn  = (const int*)  d_in[1];
    const int*   en  = (const int*)  d_in[2];
    const float* dfs = (const float*)d_in[3];
    const float* df  = (const float*)d_in[4];
    const float* W1  = (const float*)d_in[5];
    const float* b1  = (const float*)d_in[6];
    const float* W2  = (const float*)d_in[7];
    const float* b2  = (const float*)d_in[8];
    float* out = (float*)d_out;

    float *bufA, *bufB;
    cudaGetSymbolAddress((void**)&bufA, g_bufA);
    cudaGetSymbolAddress((void**)&bufB, g_bufB);
    int* offp;
    cudaGetSymbolAddress((void**)&offp, g_off);

    cudaFuncSetAttribute(mlp_kernel, cudaFuncAttributeMaxDynamicSharedMemorySize,
                         MLP_SMEM_WORDS * (int)sizeof(uint32_t));

    const bool tail = (out_size >= FULL_OUT);

    // ---- CSR build (by destination), weight split + echoes overlapped ----
    cudaMemsetAsync(offp, 0, N_NODES * sizeof(int));
    hist_and_split<<<HB + WB, 256>>>(en, W1, W2);
    scanAB<<<SCAN_BLOCKS, 256>>>();
    if (tail) {
        scanC<true><<<SCAN_BLOCKS, 256>>>(df, out);
        fill_kernel<true><<<EB, 256>>>(sn, en, dfs, out);
    } else {
        scanC<false><<<SCAN_BLOCKS, 256>>>(df, out);
        fill_kernel<false><<<EB, 256>>>(sn, en, dfs, out);
    }

    // ---- two gather passes ----
    gather_pass<<<GB, 256>>>(y,    bufA, df);
    gather_pass<<<GB, 256>>>(bufA, bufB, df);

    // ---- persistent fused tensor-core MLP (2xTF32, work-stealing) ----
    mlp_kernel<<<MLP_GRID, MLP_THREADS,
                 MLP_SMEM_WORDS * sizeof(uint32_t)>>>(bufB, b1, b2, out);
}

// round 15
// speedup vs baseline: 1.3666x; 1.0542x over previous
#include <cuda_runtime.h>
#include <cstdint>

#define N_NODES 100000
#define N_EDGES 1600000
#define DIN 48
#define DOUT 128
#define OUT_ELEMS (N_NODES * DOUT)                     // 12,800,000
#define FULL_OUT  (OUT_ELEMS + 3 * N_EDGES + N_NODES)  // 17,700,000

#define SCAN_BLOCKS ((N_NODES + 1023) / 1024)          // 98

// Scratch node-feature buffers — written fully by gather, no zeroing.
__device__ float g_bufA[(size_t)N_NODES * DIN];
__device__ float g_bufB[(size_t)N_NODES * DIN];

// CSR-by-destination structures.
__device__ int    g_off[N_NODES + 1];
__device__ int    g_rank[N_EDGES];         // rank of edge within its dest node
__device__ int    g_bsum[SCAN_BLOCKS];
__device__ int    g_scan_ctr;              // zero-init; reset by last block
__device__ int    g_mlp_ctr;               // work-stealing counter (reset by scanAB)
__device__ float2 g_epay[N_EDGES];         // {src_as_float_bits, dfs}

// Fragment-major prepacked tf32 weights (hi only; 2xTF32 scheme).
// W1f[half][nt(8)][ks(6)][lane(32)] = {W1[ks*8+c][half*64+nt*8+r], W1[ks*8+c+4][...]}
// W2f[nt(16)][kk(16)][lane(32)]     = {W2[kk*8+c][nt*8+r],        W2[kk*8+c+4][...]}
#define W1F_FRAGS (2 * 8 * 6)               // 96  -> 3072 uint2
#define W2F_FRAGS (16 * 16)                 // 256 -> 8192 uint2
__device__ uint2 g_W1f[W1F_FRAGS * 32];
__device__ uint2 g_W2f[W2F_FRAGS * 32];

// ---------------------------------------------------------------------------
// tf32 helpers.
// ---------------------------------------------------------------------------
__device__ __forceinline__ void split_tf32(float x, uint32_t& hi, uint32_t& lo)
{
    float h, l;
    asm("cvt.rna.tf32.f32 %0, %1;" : "=f"(h) : "f"(x));
    float r = x - h;
    asm("cvt.rna.tf32.f32 %0, %1;" : "=f"(l) : "f"(r));
    hi = __float_as_uint(h);
    lo = __float_as_uint(l);
}

__device__ __forceinline__ uint32_t cvt_tf32(float x)
{
    float h;
    asm("cvt.rna.tf32.f32 %0, %1;" : "=f"(h) : "f"(x));
    return __float_as_uint(h);
}

__device__ __forceinline__ void mma_tf32(float d[4],
                                         uint32_t a0, uint32_t a1, uint32_t a2, uint32_t a3,
                                         uint32_t b0, uint32_t b1)
{
    asm volatile("mma.sync.aligned.m16n8k8.row.col.f32.tf32.tf32.f32 "
                 "{%0,%1,%2,%3}, {%4,%5,%6,%7}, {%8,%9}, {%0,%1,%2,%3};"
                 : "+f"(d[0]), "+f"(d[1]), "+f"(d[2]), "+f"(d[3])
                 : "r"(a0), "r"(a1), "r"(a2), "r"(a3), "r"(b0), "r"(b1));
}

// ---------------------------------------------------------------------------
// hist (x4 edges/thread, RETURN atomics -> per-edge rank) + fragment prepack.
// ---------------------------------------------------------------------------
#define HB  ((N_EDGES / 4 + 255) / 256)     // 1563
#define WB  64                              // (3072+8192)/256 = 44 -> 64

__global__ void hist_and_split(const int* __restrict__ en,
                               const float* __restrict__ W1, const float* __restrict__ W2)
{
    if (blockIdx.x < HB) {
        int e0 = (blockIdx.x * blockDim.x + threadIdx.x) * 4;
        if (e0 + 4 <= N_EDGES) {
            int4 d4 = *(const int4*)(en + e0);
            int r0 = atomicAdd(&g_off[d4.x], 1);
            int r1 = atomicAdd(&g_off[d4.y], 1);
            int r2 = atomicAdd(&g_off[d4.z], 1);
            int r3 = atomicAdd(&g_off[d4.w], 1);
            *(int4*)(g_rank + e0) = make_int4(r0, r1, r2, r3);
        } else {
            for (int e = e0; e < N_EDGES; e++)
                g_rank[e] = atomicAdd(&g_off[__ldg(en + e)], 1);
        }
    } else {
        int i = (blockIdx.x - HB) * blockDim.x + threadIdx.x;
        if (i < W1F_FRAGS * 32) {
            int lane = i & 31;
            int frag = i >> 5;
            int ks   = frag % 6;
            int nt   = (frag / 6) & 7;
            int half = frag / 48;
            int r = lane >> 2, c = lane & 3;
            int ncol = half * 64 + nt * 8 + r;
            uint2 v;
            v.x = cvt_tf32(__ldg(W1 + (ks * 8 + c) * 128 + ncol));
            v.y = cvt_tf32(__ldg(W1 + (ks * 8 + c + 4) * 128 + ncol));
            g_W1f[i] = v;
        } else if (i < (W1F_FRAGS + W2F_FRAGS) * 32) {
            int j = i - W1F_FRAGS * 32;
            int lane = j & 31;
            int frag = j >> 5;
            int kk = frag & 15;
            int nt = frag >> 4;
            int r = lane >> 2, c = lane & 3;
            int ncol = nt * 8 + r;
            uint2 v;
            v.x = cvt_tf32(__ldg(W2 + (kk * 8 + c) * 128 + ncol));
            v.y = cvt_tf32(__ldg(W2 + (kk * 8 + c + 4) * 128 + ncol));
            g_W2f[j] = v;
        }
    }
}

// ---------------------------------------------------------------------------
// scanA+scanB fused (last-block-arrival pattern). Also resets g_mlp_ctr.
// ---------------------------------------------------------------------------
__global__ void scanAB()
{
    __shared__ int sh[256];
    __shared__ bool is_last;
    int tid = threadIdx.x;
    int base = blockIdx.x * 1024 + tid * 4;
    int s = 0;
    #pragma unroll
    for (int j = 0; j < 4; j++)
        s += (base + j < N_NODES) ? g_off[base + j] : 0;
    sh[tid] = s;
    __syncthreads();
    for (int d = 128; d > 0; d >>= 1) {
        if (tid < d) sh[tid] += sh[tid + d];
        __syncthreads();
    }
    if (tid == 0) {
        g_bsum[blockIdx.x] = sh[0];
        __threadfence();
        int c = atomicAdd(&g_scan_ctr, 1);
        is_last = (c == gridDim.x - 1);
    }
    __syncthreads();
    if (!is_last) return;

    int v = (tid < SCAN_BLOCKS) ? __ldcg(&g_bsum[tid]) : 0;
    __syncthreads();
    sh[tid] = v;
    __syncthreads();
    for (int d = 1; d < 256; d <<= 1) {
        int x = (tid >= d) ? sh[tid - d] : 0;
        __syncthreads();
        sh[tid] += x;
        __syncthreads();
    }
    if (tid < SCAN_BLOCKS) g_bsum[tid] = sh[tid] - v;
    if (tid == 0) { g_off[N_NODES] = sh[255]; g_scan_ctr = 0; g_mlp_ctr = 0; }
}

// ---------------------------------------------------------------------------
// Phase C: block-local exclusive scan + block prefix; offsets (counts -> off).
// TAIL: also echoes df into the output (coalesced DRAM STG, free here).
// ---------------------------------------------------------------------------
template <bool TAIL>
__global__ void scanC(const float* __restrict__ df, float* __restrict__ out)
{
    __shared__ int sh[256];
    int tid = threadIdx.x;
    int base = blockIdx.x * 1024 + tid * 4;
    int v[4];
    int s = 0;
    #pragma unroll
    for (int j = 0; j < 4; j++) {
        v[j] = (base + j < N_NODES) ? g_off[base + j] : 0;
        s += v[j];
    }
    sh[tid] = s;
    __syncthreads();
    for (int d = 1; d < 256; d <<= 1) {
        int x = (tid >= d) ? sh[tid - d] : 0;
        __syncthreads();
        sh[tid] += x;
        __syncthreads();
    }
    int ex = sh[tid] - s + g_bsum[blockIdx.x];
    #pragma unroll
    for (int j = 0; j < 4; j++) {
        if (base + j < N_NODES) {
            g_off[base + j] = ex;
            if (TAIL)
                out[OUT_ELEMS + 3 * N_EDGES + base + j] = __ldg(df + base + j);
        }
        ex += v[j];
    }
}

// ---------------------------------------------------------------------------
// fill: ATOMIC-FREE. pos = off[en[e]] + rank[e]. Pure loads + one STG.
// TAIL: echoes sn/en/dfs as coalesced scalar stores.
// ---------------------------------------------------------------------------
#define EB ((N_EDGES + 255) / 256)          // 6250

template <bool TAIL>
__global__ void fill_kernel(const int* __restrict__ sn, const int* __restrict__ en,
                            const float* __restrict__ dfs, float* __restrict__ out)
{
    int e = blockIdx.x * blockDim.x + threadIdx.x;
    if (e >= N_EDGES) return;
    int s = __ldg(sn + e);
    int d = __ldg(en + e);
    float f = __ldg(dfs + e);
    int pos = __ldg(&g_off[d]) + __ldg(&g_rank[e]);
    g_epay[pos] = make_float2(__int_as_float(s), f);
    if (TAIL) {
        float* p = out + OUT_ELEMS;
        p[e]               = (float)s;
        p[N_EDGES + e]     = (float)d;
        p[2 * N_EDGES + e] = f;
    }
}

// ---------------------------------------------------------------------------
// Gather pass: dst[n] = df[n] * sum_{e: end=n} src[start_e] * dfs_e
// 12 threads per node, one float4 chunk each, unrolled x4.
// ---------------------------------------------------------------------------
#define GB ((N_NODES * 12 + 255) / 256)     // 4688

__global__ void gather_pass(const float* __restrict__ src, float* __restrict__ dst,
                            const float* __restrict__ df)
{
    int t = blockIdx.x * blockDim.x + threadIdx.x;
    if (t >= N_NODES * 12) return;
    int n = t / 12;
    int q = t - n * 12;

    int o0 = __ldg(&g_off[n]);
    int o1 = __ldg(&g_off[n + 1]);

    float4 acc = make_float4(0.f, 0.f, 0.f, 0.f);
    int i = o0;
    for (; i + 4 <= o1; i += 4) {
        float2 p0 = __ldg(&g_epay[i]);
        float2 p1 = __ldg(&g_epay[i + 1]);
        float2 p2 = __ldg(&g_epay[i + 2]);
        float2 p3 = __ldg(&g_epay[i + 3]);
        float4 v0 = __ldg((const float4*)(src + (size_t)__float_as_int(p0.x) * DIN) + q);
        float4 v1 = __ldg((const float4*)(src + (size_t)__float_as_int(p1.x) * DIN) + q);
        float4 v2 = __ldg((const float4*)(src + (size_t)__float_as_int(p2.x) * DIN) + q);
        float4 v3 = __ldg((const float4*)(src + (size_t)__float_as_int(p3.x) * DIN) + q);
        acc.x = fmaf(v0.x, p0.y, acc.x); acc.y = fmaf(v0.y, p0.y, acc.y);
        acc.z = fmaf(v0.z, p0.y, acc.z); acc.w = fmaf(v0.w, p0.y, acc.w);
        acc.x = fmaf(v1.x, p1.y, acc.x); acc.y = fmaf(v1.y, p1.y, acc.y);
        acc.z = fmaf(v1.z, p1.y, acc.z); acc.w = fmaf(v1.w, p1.y, acc.w);
        acc.x = fmaf(v2.x, p2.y, acc.x); acc.y = fmaf(v2.y, p2.y, acc.y);
        acc.z = fmaf(v2.z, p2.y, acc.z); acc.w = fmaf(v2.w, p2.y, acc.w);
        acc.x = fmaf(v3.x, p3.y, acc.x); acc.y = fmaf(v3.y, p3.y, acc.y);
        acc.z = fmaf(v3.z, p3.y, acc.z); acc.w = fmaf(v3.w, p3.y, acc.w);
    }
    for (; i < o1; i++) {
        float2 p = __ldg(&g_epay[i]);
        float4 v = __ldg((const float4*)(src + (size_t)__float_as_int(p.x) * DIN) + q);
        acc.x = fmaf(v.x, p.y, acc.x); acc.y = fmaf(v.y, p.y, acc.y);
        acc.z = fmaf(v.z, p.y, acc.z); acc.w = fmaf(v.w, p.y, acc.w);
    }

    float f = __ldg(df + n);
    acc.x *= f; acc.y *= f; acc.z *= f; acc.w *= f;
    ((float4*)(dst + (size_t)n * DIN))[q] = acc;
}

// ---------------------------------------------------------------------------
// Persistent fused MLP on tensor cores (2xTF32: hi*hi + lo*hi):
//   out = relu(x @ W1 + b1) @ W2 + b2
// Fragment-major smem weights: one conflict-free LDS.64 per MMA pair at a
// compile-time immediate offset from a per-thread lane pointer (zero index
// ALU in the hot loop). 384 threads/CTA, dynamic work-stealing.
// ---------------------------------------------------------------------------
#define MLP_THREADS 384
#define MLP_GRID 148
#define N_GROUPS ((N_NODES + 15) / 16)                 // 6250
// smem: W1f 3072 uint2 | W2f 8192 uint2 | b1 128 | b2 128
#define MLP_SMEM_WORDS ((W1F_FRAGS + W2F_FRAGS) * 32 * 2 + 256)

__global__ void __launch_bounds__(MLP_THREADS, 1)
mlp_kernel(const float* __restrict__ x,
           const float* __restrict__ b1, const float* __restrict__ b2,
           float* __restrict__ out)
{
    extern __shared__ uint32_t smu[];
    uint2* W1fs = (uint2*)smu;                       // [96][32]
    uint2* W2fs = W1fs + W1F_FRAGS * 32;             // [256][32]
    float* b1s  = (float*)(W2fs + W2F_FRAGS * 32);   // [128]
    float* b2s  = b1s + 128;

    int tid = threadIdx.x;

    for (int i = tid; i < W1F_FRAGS * 32; i += MLP_THREADS) W1fs[i] = g_W1f[i];
    for (int i = tid; i < W2F_FRAGS * 32; i += MLP_THREADS) W2fs[i] = g_W2f[i];
    if (tid < 128) { b1s[tid] = __ldg(b1 + tid); b2s[tid] = __ldg(b2 + tid); }
    __syncthreads();

    int lane = tid & 31;
    int r = lane >> 2;
    int c = lane & 3;
    int srcA = (lane & ~3) | (c >> 1);
    int srcB = srcA + 2;
    bool odd = (c & 1);

    const uint2* w1p = W1fs + lane;   // + frag*32 (immediate) in the loop
    const uint2* w2p = W2fs + lane;

    while (true) {
        int g = 0;
        if (lane == 0) g = atomicAdd(&g_mlp_ctr, 1);
        g = __shfl_sync(0xFFFFFFFFu, g, 0);
        if (g >= N_GROUPS) break;

        int node0 = g * 16;
        int row0 = node0 + r;
        int row1 = row0 + 8;
        bool ok0 = row0 < N_NODES;
        bool ok1 = row1 < N_NODES;
        const float* y0 = x + (size_t)row0 * DIN;
        const float* y1 = x + (size_t)row1 * DIN;

        float d2[16][4];
        #pragma unroll
        for (int nt = 0; nt < 16; nt++) {
            d2[nt][0] = b2s[nt * 8 + 2 * c];
            d2[nt][1] = b2s[nt * 8 + 2 * c + 1];
            d2[nt][2] = d2[nt][0];
            d2[nt][3] = d2[nt][1];
        }

        #pragma unroll
        for (int half = 0; half < 2; half++) {
            // ---- stage 1 (half): H[:, half*64 .. half*64+63] ----
            float h[8][4];
            #pragma unroll
            for (int nt = 0; nt < 8; nt++) {
                int n0 = half * 64 + nt * 8;
                h[nt][0] = b1s[n0 + 2 * c];
                h[nt][1] = b1s[n0 + 2 * c + 1];
                h[nt][2] = h[nt][0];
                h[nt][3] = h[nt][1];
            }
            #pragma unroll
            for (int ks = 0; ks < 6; ks++) {
                int k0 = ks * 8;
                float a0 = ok0 ? __ldg(y0 + k0 + c)     : 0.f;
                float a1 = ok1 ? __ldg(y1 + k0 + c)     : 0.f;
                float a2 = ok0 ? __ldg(y0 + k0 + c + 4) : 0.f;
                float a3 = ok1 ? __ldg(y1 + k0 + c + 4) : 0.f;
                uint32_t ah[4], al[4];
                split_tf32(a0, ah[0], al[0]);
                split_tf32(a1, ah[1], al[1]);
                split_tf32(a2, ah[2], al[2]);
                split_tf32(a3, ah[3], al[3]);
                #pragma unroll
                for (int nt = 0; nt < 8; nt++) {
                    uint2 b = w1p[((half * 8 + nt) * 6 + ks) * 32];
                    mma_tf32(h[nt], ah[0], ah[1], ah[2], ah[3], b.x, b.y);   // hi*hi
                    mma_tf32(h[nt], al[0], al[1], al[2], al[3], b.x, b.y);   // lo*hi
                }
            }
            #pragma unroll
            for (int nt = 0; nt < 8; nt++) {
                h[nt][0] = fmaxf(h[nt][0], 0.f);
                h[nt][1] = fmaxf(h[nt][1], 0.f);
                h[nt][2] = fmaxf(h[nt][2], 0.f);
                h[nt][3] = fmaxf(h[nt][3], 0.f);
            }

            // ---- stage 2 partial: d2 += H[:, kk*8..kk*8+7] @ W2[...] ----
            #pragma unroll
            for (int ks2 = 0; ks2 < 8; ks2++) {
                int kk = half * 8 + ks2;
                float w0 = __shfl_sync(0xFFFFFFFFu, h[ks2][0], srcA);
                float w1 = __shfl_sync(0xFFFFFFFFu, h[ks2][1], srcA);
                float w2 = __shfl_sync(0xFFFFFFFFu, h[ks2][2], srcA);
                float w3 = __shfl_sync(0xFFFFFFFFu, h[ks2][3], srcA);
                float x0 = __shfl_sync(0xFFFFFFFFu, h[ks2][0], srcB);
                float x1 = __shfl_sync(0xFFFFFFFFu, h[ks2][1], srcB);
                float x2 = __shfl_sync(0xFFFFFFFFu, h[ks2][2], srcB);
                float x3 = __shfl_sync(0xFFFFFFFFu, h[ks2][3], srcB);
                uint32_t ah[4], al[4];
                split_tf32(odd ? w1 : w0, ah[0], al[0]);
                split_tf32(odd ? w3 : w2, ah[1], al[1]);
                split_tf32(odd ? x1 : x0, ah[2], al[2]);
                split_tf32(odd ? x3 : x2, ah[3], al[3]);
                #pragma unroll
                for (int nt = 0; nt < 16; nt++) {
                    uint2 b = w2p[(nt * 16 + kk) * 32];
                    mma_tf32(d2[nt], ah[0], ah[1], ah[2], ah[3], b.x, b.y);
                    mma_tf32(d2[nt], al[0], al[1], al[2], al[3], b.x, b.y);
                }
            }
        }

        // ---- store ----
        #pragma unroll
        for (int nt = 0; nt < 16; nt++) {
            if (ok0)
                *(float2*)(out + (size_t)row0 * 128 + nt * 8 + 2 * c) =
                    make_float2(d2[nt][0], d2[nt][1]);
            if (ok1)
                *(float2*)(out + (size_t)row1 * 128 + nt * 8 + 2 * c) =
                    make_float2(d2[nt][2], d2[nt][3]);
        }
    }
}

extern "C" void kernel_launch(void* const* d_in, const int* in_sizes, int n_in,
                              void* d_out, int out_size)
{
    const float* y   = (const float*)d_in[0];
    const int*   sn  = (const int*)  d_in[1];
    const int*   en  = (const int*)  d_in[2];
    const float* dfs = (const float*)d_in[3];
    const float* df  = (const float*)d_in[4];
    const float* W1  = (const float*)d_in[5];
    const float* b1  = (const float*)d_in[6];
    const float* W2  = (const float*)d_in[7];
    const float* b2  = (const float*)d_in[8];
    float* out = (float*)d_out;

    float *bufA, *bufB;
    cudaGetSymbolAddress((void**)&bufA, g_bufA);
    cudaGetSymbolAddress((void**)&bufB, g_bufB);
    int* offp;
    cudaGetSymbolAddress((void**)&offp, g_off);

    cudaFuncSetAttribute(mlp_kernel, cudaFuncAttributeMaxDynamicSharedMemorySize,
                         MLP_SMEM_WORDS * (int)sizeof(uint32_t));

    const bool tail = (out_size >= FULL_OUT);

    // ---- CSR build (by destination), fragment prepack + echoes overlapped ----
    cudaMemsetAsync(offp, 0, N_NODES * sizeof(int));
    hist_and_split<<<HB + WB, 256>>>(en, W1, W2);
    scanAB<<<SCAN_BLOCKS, 256>>>();
    if (tail) {
        scanC<true><<<SCAN_BLOCKS, 256>>>(df, out);
        fill_kernel<true><<<EB, 256>>>(sn, en, dfs, out);
    } else {
        scanC<false><<<SCAN_BLOCKS, 256>>>(df, out);
        fill_kernel<false><<<EB, 256>>>(sn, en, dfs, out);
    }

    // ---- two gather passes ----
    gather_pass<<<GB, 256>>>(y,    bufA, df);
    gather_pass<<<GB, 256>>>(bufA, bufB, df);

    // ---- persistent fused tensor-core MLP (2xTF32, fragment-major weights) ----
    mlp_kernel<<<MLP_GRID, MLP_THREADS,
                 MLP_SMEM_WORDS * sizeof(uint32_t)>>>(bufB, b1, b2, out);
}